// round 3
// baseline (speedup 1.0000x reference)
#include <cuda_runtime.h>
#include <math.h>

// ---------------- problem constants ----------------
#define cL    64
#define cEMB  128
#define cH2   128
#define cG3   384      /* 3*H2 */
#define cEXC  256
#define cHID  256
#define cN    200000
#define cK    10

#define OUT_PRED 0L
#define OUT_EXCS 1L
#define OUT_HS   (1L + (long)(cN + 1) * cEXC)   /* 51200257 */

#define NBLK  148                 /* fused kernel grid: 2 GRU + 146 workers */
#define NWRK  146
#define TPB   1024
#define NWARPS_GEMV (NWRK * 32)   /* 4672 */
#define NCAND (NWRK * cK)         /* 1460 */

// GRU smem: W 49152 + hbuf 256 + gsh 384 + gin 128 = 49920 floats
#define FUSED_SMEM_FLOATS 49920

// ---------------- device scratch (no allocs allowed) ----------------
__device__ float g_gi[2][cL][cG3];   // precomputed input gates, both dirs
__device__ float g_exc[cEXC];        // max-pooled exercise embedding
__device__ float g_cv[NCAND];        // per-block top-k candidate values
__device__ int   g_ci[NCAND];        // per-block top-k candidate indices
__device__ float g_giv[3 * cHID];    // seq-GRU input-gate preacts
__device__ float g_ghv[3 * cHID];    // seq-GRU hidden-gate preacts
__device__ int   g_gru_done;         // 2 == exc ready (reset at end of kernel)
__device__ int   g_ticket;           // block completion ticket (reset at end)

__device__ __forceinline__ float sigmoidf_(float x) {
    return 1.0f / (1.0f + expf(-x));
}

// ============================================================
// K0: gi[dir][s][t] = bih[t] + dot(emb[exec_ids[idx]], Wih[t])
// ============================================================
__global__ void gi_kernel(const int* __restrict__ exec_ids,
                          const float* __restrict__ emb,
                          const float* __restrict__ wf_Wih,
                          const float* __restrict__ wf_bih,
                          const float* __restrict__ wb_Wih,
                          const float* __restrict__ wb_bih) {
    __shared__ __align__(16) float xs[cEMB];
    int b = blockIdx.x;
    int dir = b >> 6;
    int s = b & 63;
    int row = dir ? (cL - 1 - s) : s;
    int t = threadIdx.x;

    const float* Wih = dir ? wb_Wih : wf_Wih;
    const float* bih = dir ? wb_bih : wf_bih;

    if (t < 32) {
        int wid = exec_ids[row];
        ((float4*)xs)[t] = ((const float4*)(emb + (long)wid * cEMB))[t];
    }
    __syncthreads();

    const float4* w4 = (const float4*)(Wih + (long)t * cEMB);
    const float4* x4 = (const float4*)xs;
    float a0 = 0.f, a1 = 0.f;
#pragma unroll
    for (int k = 0; k < 32; k += 2) {
        float4 w = w4[k];     float4 x = x4[k];
        a0 += w.x * x.x + w.y * x.y + w.z * x.z + w.w * x.w;
        float4 w2 = w4[k + 1]; float4 x2 = x4[k + 1];
        a1 += w2.x * x2.x + w2.y * x2.y + w2.z * x2.z + w2.w * x2.w;
    }
    g_gi[dir][s][t] = a0 + a1 + bih[t];
}

// ============================================================
// K1: fully fused persistent kernel (148 blocks, 1024 threads)
// ============================================================
__global__ void __launch_bounds__(TPB, 1)
fused_kernel(const float* __restrict__ score,
             const float* __restrict__ excs,
             const float* __restrict__ hs,
             const float* __restrict__ wf_Whh, const float* __restrict__ wf_bhh,
             const float* __restrict__ wb_Whh, const float* __restrict__ wb_bhh,
             const float* __restrict__ s_Wih,  const float* __restrict__ s_Whh,
             const float* __restrict__ s_bih,  const float* __restrict__ s_bhh,
             const float* __restrict__ out_W,  const float* __restrict__ out_b,
             float* __restrict__ out) {
    extern __shared__ float sm[];
    __shared__ int is_last;
    int t = threadIdx.x;
    int lane = t & 31;
    int warp = t >> 5;
    int b = blockIdx.x;

    if (b < 2) {
        // ================= GRU recurrence (dir = b) =================
        int dir = b;
        float* Wsh  = sm;                        // 49152
        float* hbuf = sm + cG3 * cH2;            // 256 (double buffer)
        float* gsh  = hbuf + 256;                // 384
        float* gin  = gsh + 384;                 // 128 (inn gi pass-through)

        const float* Whh = dir ? wb_Whh : wf_Whh;
        const float* bhh = dir ? wb_bhh : wf_bhh;

        // stage Whh: W4[kk*384 + t] = Whh[t][4kk..4kk+3]
        for (int idx = t; idx < cG3 * cH2 / 4; idx += TPB) {
            int kk = idx / cG3;
            int tt = idx - kk * cG3;
            ((float4*)Wsh)[idx] = *(const float4*)(Whh + (long)tt * cH2 + kk * 4);
        }
        if (t < cH2) hbuf[t] = 0.0f;
        float bhh_t = (t < cG3) ? bhh[t] : 0.0f;
        float gi_cur = (t < cG3) ? g_gi[dir][0][t] : 0.0f;
        float hmax = -1e30f;
        __syncthreads();

        const float4* W4 = ((const float4*)Wsh) + t;
        for (int s = 0; s < cL; ++s) {
            // prefetch next step's gi (covers DRAM/L2 latency under the gemv)
            float gi_nxt = (t < cG3 && s + 1 < cL) ? g_gi[dir][s + 1][t] : 0.0f;
            float* hcur = hbuf + ((s & 1) ? 128 : 0);
            float* hnxt = hbuf + ((s & 1) ? 0 : 128);

            if (t < cG3) {
                const float4* h4 = (const float4*)hcur;
                float a0 = 0.f, a1 = 0.f;
#pragma unroll
                for (int kk = 0; kk < 32; kk += 2) {
                    float4 w = W4[kk * cG3];        float4 hv = h4[kk];
                    a0 += w.x * hv.x + w.y * hv.y + w.z * hv.z + w.w * hv.w;
                    float4 w2 = W4[(kk + 1) * cG3]; float4 hv2 = h4[kk + 1];
                    a1 += w2.x * hv2.x + w2.y * hv2.y + w2.z * hv2.z + w2.w * hv2.w;
                }
                float gh = a0 + a1 + bhh_t;
                if (t < 256) {
                    gsh[t] = sigmoidf_(gi_cur + gh);
                } else {
                    gsh[t] = gh;
                    gin[t - 256] = gi_cur;
                }
            }
            __syncthreads();

            if (t < cH2) {
                float r = gsh[t];
                float z = gsh[128 + t];
                float n = tanhf(gin[t] + r * gsh[256 + t]);
                float hn = (1.0f - z) * n + z * hcur[t];
                hnxt[t] = hn;
                hmax = fmaxf(hmax, hn);
            }
            __syncthreads();
            gi_cur = gi_nxt;
        }
        if (t < cH2) g_exc[dir * cH2 + t] = hmax;
        __threadfence();
        __syncthreads();
        if (t == 0) atomicAdd(&g_gru_done, 1);

        // wait for the peer direction
        if (t == 0) {
            while (*(volatile int*)&g_gru_done < 2) __nanosleep(64);
        }
        __syncthreads();
        __threadfence();

        // ---- seq-GRU gate preactivations: this block handles 384 gates ----
        float* exc_sh = sm;          // reuse smem (W no longer needed)
        float* h_sh   = sm + 256;
        if (t < 256) exc_sh[t] = g_exc[t];
        else if (t < 512) h_sh[t - 256] = hs[(long)(cN - 1) * cHID + (t - 256)];
        __syncthreads();

        int off = (score[0] >= 0.5f) ? 0 : 256;    // nonzero half of xin
        const float4* x4  = (const float4*)exc_sh;
        const float4* hh4 = (const float4*)h_sh;
#pragma unroll
        for (int j = 0; j < 12; ++j) {
            int g = dir * 384 + warp * 12 + j;     // gate id
            const float4* wi4 = (const float4*)(s_Wih + (long)g * 512 + off);
            const float4* wh4 = (const float4*)(s_Whh + (long)g * 256);

            float4 a = wi4[lane];       float4 xa = x4[lane];
            float4 bb = wi4[lane + 32]; float4 xb = x4[lane + 32];
            float giv = a.x * xa.x + a.y * xa.y + a.z * xa.z + a.w * xa.w
                      + bb.x * xb.x + bb.y * xb.y + bb.z * xb.z + bb.w * xb.w;

            float4 c = wh4[lane];       float4 hc = hh4[lane];
            float4 d = wh4[lane + 32];  float4 hd = hh4[lane + 32];
            float ghv = c.x * hc.x + c.y * hc.y + c.z * hc.z + c.w * hc.w
                      + d.x * hd.x + d.y * hd.y + d.z * hd.z + d.w * hd.w;
#pragma unroll
            for (int o = 16; o; o >>= 1) {
                giv += __shfl_xor_sync(0xffffffffu, giv, o);
                ghv += __shfl_xor_sync(0xffffffffu, ghv, o);
            }
            if (lane == 0) {
                g_giv[g] = giv + s_bih[g];
                g_ghv[g] = ghv + s_bhh[g];
            }
        }
        __threadfence();
        __syncthreads();
    } else {
        // ================= worker block =================
        int wb = b - 2;

        // ---- phase 1: stream copy hs -> out[OUT_HS] ----
        const float4* src = (const float4*)hs;
        float* dst = out + OUT_HS;
        const long nchunk = (long)cN * cHID / 16;   // 3,200,000
        const long stride = (long)NWRK * TPB;
        for (long c = (long)wb * TPB + t; c < nchunk; c += stride) {
            long i = c * 4;
            float4 v0 = __ldcs(src + i);
            float4 v1 = __ldcs(src + i + 1);
            float4 v2 = __ldcs(src + i + 2);
            float4 v3 = __ldcs(src + i + 3);
            long o = i * 4;
            __stcs(dst + o + 0,  v0.x); __stcs(dst + o + 1,  v0.y);
            __stcs(dst + o + 2,  v0.z); __stcs(dst + o + 3,  v0.w);
            __stcs(dst + o + 4,  v1.x); __stcs(dst + o + 5,  v1.y);
            __stcs(dst + o + 6,  v1.z); __stcs(dst + o + 7,  v1.w);
            __stcs(dst + o + 8,  v2.x); __stcs(dst + o + 9,  v2.y);
            __stcs(dst + o + 10, v2.z); __stcs(dst + o + 11, v2.w);
            __stcs(dst + o + 12, v3.x); __stcs(dst + o + 13, v3.y);
            __stcs(dst + o + 14, v3.z); __stcs(dst + o + 15, v3.w);
        }

        // ---- wait for exc ----
        if (t == 0) {
            while (*(volatile int*)&g_gru_done < 2) __nanosleep(128);
        }
        __syncthreads();
        __threadfence();

        float* exc_sh = sm;                 // 256
        float* wv = sm + 256;               // 320
        int*   wis = (int*)(sm + 256 + 320);// 320
        if (t < cEXC) exc_sh[t] = g_exc[t];
        __syncthreads();

        // ---- phase 2: fused excs copy + alpha gemv + warp top-10 ----
        float tv[cK]; int ti[cK];
#pragma unroll
        for (int j = 0; j < cK; ++j) { tv[j] = -1e30f; ti[j] = 0; }

        float* dste = out + OUT_EXCS;
        const int c0 = lane * 4;
        const float e0 = exc_sh[c0],           e1 = exc_sh[c0 + 1];
        const float e2 = exc_sh[c0 + 2],       e3 = exc_sh[c0 + 3];
        const float f0 = exc_sh[128 + c0],     f1 = exc_sh[128 + c0 + 1];
        const float f2 = exc_sh[128 + c0 + 2], f3 = exc_sh[128 + c0 + 3];

        int r = wb * 32 + warp;
        for (; r + NWARPS_GEMV < cN; r += 2 * NWARPS_GEMV) {
            const float4* rp1 = (const float4*)(excs + (long)r * cEXC);
            const float4* rp2 = (const float4*)(excs + (long)(r + NWARPS_GEMV) * cEXC);
            float4 a1 = __ldcs(rp1 + lane), b1 = __ldcs(rp1 + 32 + lane);
            float4 a2 = __ldcs(rp2 + lane), b2 = __ldcs(rp2 + 32 + lane);

            float* d1 = dste + (long)r * cEXC;
            __stcs(d1 + c0 + 0, a1.x); __stcs(d1 + c0 + 1, a1.y);
            __stcs(d1 + c0 + 2, a1.z); __stcs(d1 + c0 + 3, a1.w);
            __stcs(d1 + 128 + c0 + 0, b1.x); __stcs(d1 + 128 + c0 + 1, b1.y);
            __stcs(d1 + 128 + c0 + 2, b1.z); __stcs(d1 + 128 + c0 + 3, b1.w);
            float* d2 = dste + (long)(r + NWARPS_GEMV) * cEXC;
            __stcs(d2 + c0 + 0, a2.x); __stcs(d2 + c0 + 1, a2.y);
            __stcs(d2 + c0 + 2, a2.z); __stcs(d2 + c0 + 3, a2.w);
            __stcs(d2 + 128 + c0 + 0, b2.x); __stcs(d2 + 128 + c0 + 1, b2.y);
            __stcs(d2 + 128 + c0 + 2, b2.z); __stcs(d2 + 128 + c0 + 3, b2.w);

            float p1 = a1.x * e0 + a1.y * e1 + a1.z * e2 + a1.w * e3
                     + b1.x * f0 + b1.y * f1 + b1.z * f2 + b1.w * f3;
            float p2 = a2.x * e0 + a2.y * e1 + a2.z * e2 + a2.w * e3
                     + b2.x * f0 + b2.y * f1 + b2.z * f2 + b2.w * f3;
#pragma unroll
            for (int o = 16; o; o >>= 1) {
                p1 += __shfl_xor_sync(0xffffffffu, p1, o);
                p2 += __shfl_xor_sync(0xffffffffu, p2, o);
            }
            if (p1 > tv[cK - 1]) {
                int pos = cK - 1;
#pragma unroll
                for (int j = cK - 1; j > 0; --j)
                    if (tv[j - 1] < p1) { tv[j] = tv[j - 1]; ti[j] = ti[j - 1]; pos = j - 1; }
                tv[pos] = p1; ti[pos] = r;
            }
            if (p2 > tv[cK - 1]) {
                int pos = cK - 1;
#pragma unroll
                for (int j = cK - 1; j > 0; --j)
                    if (tv[j - 1] < p2) { tv[j] = tv[j - 1]; ti[j] = ti[j - 1]; pos = j - 1; }
                tv[pos] = p2; ti[pos] = r + NWARPS_GEMV;
            }
        }
        if (r < cN) {
            const float4* rp = (const float4*)(excs + (long)r * cEXC);
            float4 a = __ldcs(rp + lane), bb = __ldcs(rp + 32 + lane);
            float* d = dste + (long)r * cEXC;
            __stcs(d + c0 + 0, a.x); __stcs(d + c0 + 1, a.y);
            __stcs(d + c0 + 2, a.z); __stcs(d + c0 + 3, a.w);
            __stcs(d + 128 + c0 + 0, bb.x); __stcs(d + 128 + c0 + 1, bb.y);
            __stcs(d + 128 + c0 + 2, bb.z); __stcs(d + 128 + c0 + 3, bb.w);
            float p = a.x * e0 + a.y * e1 + a.z * e2 + a.w * e3
                    + bb.x * f0 + bb.y * f1 + bb.z * f2 + bb.w * f3;
#pragma unroll
            for (int o = 16; o; o >>= 1) p += __shfl_xor_sync(0xffffffffu, p, o);
            if (p > tv[cK - 1]) {
                int pos = cK - 1;
#pragma unroll
                for (int j = cK - 1; j > 0; --j)
                    if (tv[j - 1] < p) { tv[j] = tv[j - 1]; ti[j] = ti[j - 1]; pos = j - 1; }
                tv[pos] = p; ti[pos] = r;
            }
        }

        if (lane == 0) {
#pragma unroll
            for (int j = 0; j < cK; ++j) {
                wv[warp * cK + j] = tv[j];
                wis[warp * cK + j] = ti[j];
            }
        }
        __syncthreads();

        // ---- block merge: warp 0 does 10 rounds of 320-way argmax ----
        if (warp == 0) {
            for (int j = 0; j < cK; ++j) {
                float bv = -3e30f; int bm = 0;
                for (int m = lane; m < 320; m += 32)
                    if (wv[m] > bv) { bv = wv[m]; bm = m; }
#pragma unroll
                for (int o = 16; o; o >>= 1) {
                    float ov = __shfl_xor_sync(0xffffffffu, bv, o);
                    int   om = __shfl_xor_sync(0xffffffffu, bm, o);
                    if (ov > bv) { bv = ov; bm = om; }
                }
                if (lane == 0) {
                    g_cv[wb * cK + j] = bv;
                    g_ci[wb * cK + j] = wis[bm];
                    wv[bm] = -3e30f;
                }
                __syncwarp();
                __threadfence_block();
            }
        }
        __threadfence();
        __syncthreads();
    }

    // ================= completion ticket =================
    if (t == 0) {
        int v = atomicAdd(&g_ticket, 1);
        is_last = (v == NBLK - 1);
    }
    __syncthreads();
    if (!is_last) return;
    __threadfence();

    // ================= FINAL (runs on the last-finishing block) ==========
    {
        float* cv   = sm;                   // 1460
        int*   ci   = (int*)(sm + 1536);    // 1460
        float* mv   = sm + 3072;            // 1024
        int*   mi   = (int*)(sm + 4096);    // 1024
        float* topv = sm + 5120;            // 10
        float* wgt  = sm + 5136;            // 10
        int*   topi = (int*)(sm + 5152);    // 10
        float* exc2 = sm + 5184;            // 256
        float* h2   = sm + 5440;            // 256
        float* attn = sm + 5696;            // 256
        float* red  = sm + 5952;            // 512

        __syncthreads();
        for (int i = t; i < NCAND; i += TPB) { cv[i] = g_cv[i]; ci[i] = g_ci[i]; }
        if (t < cEXC) exc2[t] = g_exc[t];
        else if (t < 512) h2[t - 256] = hs[(long)(cN - 1) * cHID + (t - 256)];
        __syncthreads();

        // global top-10 by repeated parallel argmax
        for (int j = 0; j < cK; ++j) {
            float bv = -1e30f; int bi = 0;
            for (int i = t; i < NCAND; i += TPB)
                if (cv[i] > bv) { bv = cv[i]; bi = i; }
            mv[t] = bv; mi[t] = bi;
            __syncthreads();
            for (int sft = 512; sft; sft >>= 1) {
                if (t < sft) {
                    if (mv[t + sft] > mv[t]) { mv[t] = mv[t + sft]; mi[t] = mi[t + sft]; }
                }
                __syncthreads();
            }
            if (t == 0) {
                topv[j] = mv[0];
                topi[j] = ci[mi[0]];
                cv[mi[0]] = -3e30f;
            }
            __syncthreads();
        }

        if (t == 0) {
            float mx = topv[0];
            float ssum = 0.f;
            for (int j = 0; j < cK; ++j) { wgt[j] = expf(topv[j] - mx); ssum += wgt[j]; }
            for (int j = 0; j < cK; ++j) wgt[j] /= ssum;
        }
        __syncthreads();

        if (t < cHID) {
            float a = 0.f;
#pragma unroll
            for (int j = 0; j < cK; ++j)
                a += wgt[j] * hs[(long)topi[j] * cHID + t];
            attn[t] = a;
        }
        __syncthreads();

        // pred
        if (t < 512) {
            float v = (t < cEXC) ? exc2[t] : attn[t - cEXC];
            red[t] = v * out_W[t];
        }
        __syncthreads();
        for (int sft = 256; sft; sft >>= 1) {
            if (t < sft) red[t] += red[t + sft];
            __syncthreads();
        }
        if (t == 0) out[OUT_PRED] = red[0] + out_b[0];

        // seq-GRU combine + appended rows
        if (t < cHID) {
            float rr = sigmoidf_(g_giv[t] + g_ghv[t]);
            float zz = sigmoidf_(g_giv[cHID + t] + g_ghv[cHID + t]);
            float nn = tanhf(g_giv[2 * cHID + t] + rr * g_ghv[2 * cHID + t]);
            float hn = (1.0f - zz) * nn + zz * h2[t];
            out[OUT_HS + (long)cN * cHID + t] = hn;
        }
        if (t < cEXC)
            out[OUT_EXCS + (long)cN * cEXC + t] = exc2[t];

        // reset counters for the next graph replay
        if (t == 0) {
            g_gru_done = 0;
            g_ticket = 0;
        }
    }
}

// ============================================================
extern "C" void kernel_launch(void* const* d_in, const int* in_sizes, int n_in,
                              void* d_out, int out_size) {
    const int*   exec_ids = (const int*)d_in[0];
    const float* score    = (const float*)d_in[1];
    const float* excs     = (const float*)d_in[2];
    const float* hs       = (const float*)d_in[3];
    const float* emb      = (const float*)d_in[4];
    const float* wf_Wih   = (const float*)d_in[5];
    const float* wf_Whh   = (const float*)d_in[6];
    const float* wf_bih   = (const float*)d_in[7];
    const float* wf_bhh   = (const float*)d_in[8];
    const float* wb_Wih   = (const float*)d_in[9];
    const float* wb_Whh   = (const float*)d_in[10];
    const float* wb_bih   = (const float*)d_in[11];
    const float* wb_bhh   = (const float*)d_in[12];
    const float* s_Wih    = (const float*)d_in[13];
    const float* s_Whh    = (const float*)d_in[14];
    const float* s_bih    = (const float*)d_in[15];
    const float* s_bhh    = (const float*)d_in[16];
    const float* out_W    = (const float*)d_in[17];
    const float* out_b    = (const float*)d_in[18];
    float* out = (float*)d_out;

    const int fused_smem = FUSED_SMEM_FLOATS * sizeof(float);  // 199,680 B
    cudaFuncSetAttribute(fused_kernel,
                         cudaFuncAttributeMaxDynamicSharedMemorySize, fused_smem);

    gi_kernel<<<128, 384>>>(exec_ids, emb, wf_Wih, wf_bih, wb_Wih, wb_bih);
    fused_kernel<<<NBLK, TPB, fused_smem>>>(score, excs, hs,
                                            wf_Whh, wf_bhh, wb_Whh, wb_bhh,
                                            s_Wih, s_Whh, s_bih, s_bhh,
                                            out_W, out_b, out);
}

// round 4
// speedup vs baseline: 1.7040x; 1.7040x over previous
#include <cuda_runtime.h>
#include <math.h>

// ---------------- problem constants ----------------
#define cL    64
#define cEMB  128
#define cH2   128
#define cG3   384      /* 3*H2 */
#define cEXC  256
#define cHID  256
#define cN    200000
#define cK    10

#define OUT_PRED 0L
#define OUT_EXCS 1L
#define OUT_HS   (1L + (long)(cN + 1) * cEXC)   /* 51200257 */

#define NBLK  148                 /* fused kernel grid: 2 GRU + 146 workers */
#define NWRK  146
#define TPB   512
#define WPB   16                  /* warps per block */
#define NWARPS_GEMV (NWRK * WPB)  /* 2336 */
#define NCAND (NWRK * cK)         /* 1460 */
#define FULLM 0xffffffffu

// GRU smem: W 49152 + hbuf 256 + gsh 384 + gin 128 = 49920 floats
#define FUSED_SMEM_FLOATS 49920

// ---------------- device scratch (no allocs allowed) ----------------
__device__ float g_gi[2][cL][cG3];   // precomputed input gates, both dirs
__device__ float g_exc[cEXC];        // max-pooled exercise embedding
__device__ float g_cv[NCAND];        // per-block top-k candidate values
__device__ int   g_ci[NCAND];        // per-block top-k candidate indices
__device__ float g_giv[3 * cHID];    // seq-GRU input-gate preacts
__device__ float g_ghv[3 * cHID];    // seq-GRU hidden-gate preacts
__device__ int   g_gru_done;         // 2 == exc ready (reset at end of kernel)
__device__ int   g_ticket;           // block completion ticket (reset at end)

__device__ __forceinline__ float sigmoidf_(float x) {
    return 1.0f / (1.0f + expf(-x));
}

// ============================================================
// K0: gi[dir][s][t] = bih[t] + dot(emb[exec_ids[idx]], Wih[t])
// ============================================================
__global__ void gi_kernel(const int* __restrict__ exec_ids,
                          const float* __restrict__ emb,
                          const float* __restrict__ wf_Wih,
                          const float* __restrict__ wf_bih,
                          const float* __restrict__ wb_Wih,
                          const float* __restrict__ wb_bih) {
    __shared__ __align__(16) float xs[cEMB];
    int b = blockIdx.x;
    int dir = b >> 6;
    int s = b & 63;
    int row = dir ? (cL - 1 - s) : s;
    int t = threadIdx.x;

    const float* Wih = dir ? wb_Wih : wf_Wih;
    const float* bih = dir ? wb_bih : wf_bih;

    if (t < 32) {
        int wid = exec_ids[row];
        ((float4*)xs)[t] = ((const float4*)(emb + (long)wid * cEMB))[t];
    }
    __syncthreads();

    const float4* w4 = (const float4*)(Wih + (long)t * cEMB);
    const float4* x4 = (const float4*)xs;
    float a0 = 0.f, a1 = 0.f;
#pragma unroll
    for (int k = 0; k < 32; k += 2) {
        float4 w = w4[k];     float4 x = x4[k];
        a0 += w.x * x.x + w.y * x.y + w.z * x.z + w.w * x.w;
        float4 w2 = w4[k + 1]; float4 x2 = x4[k + 1];
        a1 += w2.x * x2.x + w2.y * x2.y + w2.z * x2.z + w2.w * x2.w;
    }
    g_gi[dir][s][t] = a0 + a1 + bih[t];
}

// ============================================================
// K1: fused persistent kernel (148 blocks x 512 threads, 1 wave)
// ============================================================
__global__ void __launch_bounds__(TPB, 1)
fused_kernel(const float* __restrict__ score,
             const float* __restrict__ excs,
             const float* __restrict__ hs,
             const float* __restrict__ wf_Whh, const float* __restrict__ wf_bhh,
             const float* __restrict__ wb_Whh, const float* __restrict__ wb_bhh,
             const float* __restrict__ s_Wih,  const float* __restrict__ s_Whh,
             const float* __restrict__ s_bih,  const float* __restrict__ s_bhh,
             const float* __restrict__ out_W,  const float* __restrict__ out_b,
             float* __restrict__ out) {
    extern __shared__ float sm[];
    __shared__ int is_last;
    int t = threadIdx.x;
    int lane = t & 31;
    int warp = t >> 5;
    int b = blockIdx.x;

    if (b < 2) {
        // ================= GRU recurrence (dir = b) =================
        int dir = b;
        float* Wsh  = sm;                        // 49152
        float* hbuf = sm + cG3 * cH2;            // 256 (double buffer)
        float* gsh  = hbuf + 256;                // 384
        float* gin  = gsh + 384;                 // 128

        const float* Whh = dir ? wb_Whh : wf_Whh;
        const float* bhh = dir ? wb_bhh : wf_bhh;

        for (int idx = t; idx < cG3 * cH2 / 4; idx += TPB) {
            int kk = idx / cG3;
            int tt = idx - kk * cG3;
            ((float4*)Wsh)[idx] = *(const float4*)(Whh + (long)tt * cH2 + kk * 4);
        }
        if (t < cH2) hbuf[t] = 0.0f;
        float bhh_t = (t < cG3) ? bhh[t] : 0.0f;
        float gi_cur = (t < cG3) ? g_gi[dir][0][t] : 0.0f;
        float hmax = -1e30f;
        __syncthreads();

        const float4* W4 = ((const float4*)Wsh) + t;
        for (int s = 0; s < cL; ++s) {
            float gi_nxt = (t < cG3 && s + 1 < cL) ? g_gi[dir][s + 1][t] : 0.0f;
            float* hcur = hbuf + ((s & 1) ? 128 : 0);
            float* hnxt = hbuf + ((s & 1) ? 0 : 128);

            if (t < cG3) {
                const float4* h4 = (const float4*)hcur;
                float a0 = 0.f, a1 = 0.f;
#pragma unroll
                for (int kk = 0; kk < 32; kk += 2) {
                    float4 w = W4[kk * cG3];        float4 hv = h4[kk];
                    a0 += w.x * hv.x + w.y * hv.y + w.z * hv.z + w.w * hv.w;
                    float4 w2 = W4[(kk + 1) * cG3]; float4 hv2 = h4[kk + 1];
                    a1 += w2.x * hv2.x + w2.y * hv2.y + w2.z * hv2.z + w2.w * hv2.w;
                }
                float gh = a0 + a1 + bhh_t;
                if (t < 256) {
                    gsh[t] = sigmoidf_(gi_cur + gh);
                } else {
                    gsh[t] = gh;
                    gin[t - 256] = gi_cur;
                }
            }
            __syncthreads();

            if (t < cH2) {
                float r = gsh[t];
                float z = gsh[128 + t];
                float n = tanhf(gin[t] + r * gsh[256 + t]);
                float hn = (1.0f - z) * n + z * hcur[t];
                hnxt[t] = hn;
                hmax = fmaxf(hmax, hn);
            }
            __syncthreads();
            gi_cur = gi_nxt;
        }
        if (t < cH2) g_exc[dir * cH2 + t] = hmax;
        __threadfence();
        __syncthreads();
        if (t == 0) atomicAdd(&g_gru_done, 1);

        if (t == 0) {
            while (*(volatile int*)&g_gru_done < 2) __nanosleep(64);
        }
        __syncthreads();
        __threadfence();

        // ---- seq-GRU gate preacts: this block handles 384 gates ----
        float* exc_sh = sm;
        float* h_sh   = sm + 256;
        if (t < 256) exc_sh[t] = g_exc[t];
        else if (t < 512) h_sh[t - 256] = hs[(long)(cN - 1) * cHID + (t - 256)];
        __syncthreads();

        int off = (score[0] >= 0.5f) ? 0 : 256;
        const float4* x4  = (const float4*)exc_sh;
        const float4* hh4 = (const float4*)h_sh;
#pragma unroll
        for (int j = 0; j < 24; ++j) {
            int g = dir * 384 + warp * 24 + j;
            const float4* wi4 = (const float4*)(s_Wih + (long)g * 512 + off);
            const float4* wh4 = (const float4*)(s_Whh + (long)g * 256);

            float4 a = wi4[lane];       float4 xa = x4[lane];
            float4 bb = wi4[lane + 32]; float4 xb = x4[lane + 32];
            float giv = a.x * xa.x + a.y * xa.y + a.z * xa.z + a.w * xa.w
                      + bb.x * xb.x + bb.y * xb.y + bb.z * xb.z + bb.w * xb.w;

            float4 c = wh4[lane];       float4 hc = hh4[lane];
            float4 d = wh4[lane + 32];  float4 hd = hh4[lane + 32];
            float ghv = c.x * hc.x + c.y * hc.y + c.z * hc.z + c.w * hc.w
                      + d.x * hd.x + d.y * hd.y + d.z * hd.z + d.w * hd.w;
#pragma unroll
            for (int o = 16; o; o >>= 1) {
                giv += __shfl_xor_sync(FULLM, giv, o);
                ghv += __shfl_xor_sync(FULLM, ghv, o);
            }
            if (lane == 0) {
                g_giv[g] = giv + s_bih[g];
                g_ghv[g] = ghv + s_bhh[g];
            }
        }
        __threadfence();
        __syncthreads();
    } else {
        // ================= worker block =================
        int wb = b - 2;

        // head/tail scalars of the misaligned hs region
        if (wb == 0 && t == 0) {
            out[OUT_HS + 0] = hs[0];
            out[OUT_HS + 1] = hs[1];
            out[OUT_HS + 2] = hs[2];
            out[OUT_HS + (long)cN * cHID - 1] = hs[(long)cN * cHID - 1];
        }

        // ---- phase 1: stream copy hs -> out[OUT_HS], aligned STG.128 ----
        // out4[n] = (hs[4n+3], hs4[n+1].xyz), n in [0, Q)
        {
            const float4* s4 = (const float4*)hs;
            float4* d4 = (float4*)(out + OUT_HS + 3);   // 16B aligned
            const long Q = (long)cN * cHID / 4 - 1;     // 12,799,999
            const long big = (long)NWRK * TPB * 4;
            for (long base = (long)wb * (TPB * 4); base < Q; base += big) {
                long n0 = base + t;
                long n1 = n0 + TPB;
                long n2 = n1 + TPB;
                long n3 = n2 + TPB;
                float4 v0, v1, v2, v3;
                if (n0 < Q) v0 = __ldcs(s4 + n0 + 1);
                if (n1 < Q) v1 = __ldcs(s4 + n1 + 1);
                if (n2 < Q) v2 = __ldcs(s4 + n2 + 1);
                if (n3 < Q) v3 = __ldcs(s4 + n3 + 1);

                float p0 = __shfl_up_sync(FULLM, v0.w, 1);
                float p1 = __shfl_up_sync(FULLM, v1.w, 1);
                float p2 = __shfl_up_sync(FULLM, v2.w, 1);
                float p3 = __shfl_up_sync(FULLM, v3.w, 1);
                if (lane == 0) {
                    if (n0 < Q) p0 = __ldcs(hs + 4 * n0 + 3);
                    if (n1 < Q) p1 = __ldcs(hs + 4 * n1 + 3);
                    if (n2 < Q) p2 = __ldcs(hs + 4 * n2 + 3);
                    if (n3 < Q) p3 = __ldcs(hs + 4 * n3 + 3);
                }
                if (n0 < Q) __stcs(d4 + n0, make_float4(p0, v0.x, v0.y, v0.z));
                if (n1 < Q) __stcs(d4 + n1, make_float4(p1, v1.x, v1.y, v1.z));
                if (n2 < Q) __stcs(d4 + n2, make_float4(p2, v2.x, v2.y, v2.z));
                if (n3 < Q) __stcs(d4 + n3, make_float4(p3, v3.x, v3.y, v3.z));
            }
        }

        // ---- wait for exc ----
        if (t == 0) {
            while (*(volatile int*)&g_gru_done < 2) __nanosleep(128);
        }
        __syncthreads();
        __threadfence();

        float* exc_sh = sm;                       // 256
        float* wv = sm + 256;                     // WPB*10
        int*   wis = (int*)(sm + 256 + WPB * cK); // WPB*10
        if (t < cEXC) exc_sh[t] = g_exc[t];
        __syncthreads();

        // ---- phase 2: fused excs copy + alpha gemv + warp top-10 ----
        float tv[cK]; int ti[cK];
#pragma unroll
        for (int j = 0; j < cK; ++j) { tv[j] = -1e30f; ti[j] = 0; }

        const int c0 = lane * 4;
        const float e0 = exc_sh[c0],           e1 = exc_sh[c0 + 1];
        const float e2 = exc_sh[c0 + 2],       e3 = exc_sh[c0 + 3];
        const float f0 = exc_sh[128 + c0],     f1 = exc_sh[128 + c0 + 1];
        const float f2 = exc_sh[128 + c0 + 2], f3 = exc_sh[128 + c0 + 3];

#define ROW_BODY(RR)                                                          \
        {                                                                     \
            const float4* rp = (const float4*)(excs + (long)(RR) * cEXC);     \
            float4 a = __ldcs(rp + lane);                                     \
            float4 bb = __ldcs(rp + 32 + lane);                               \
            float p = a.x * e0 + a.y * e1 + a.z * e2 + a.w * e3               \
                    + bb.x * f0 + bb.y * f1 + bb.z * f2 + bb.w * f3;          \
            _Pragma("unroll")                                                 \
            for (int o = 16; o; o >>= 1) p += __shfl_xor_sync(FULLM, p, o);   \
            float* drow = out + OUT_EXCS + (long)(RR) * cEXC;                 \
            if (lane == 0) { drow[0] = a.x; drow[1] = a.y; drow[2] = a.z; }   \
            float4* d4r = (float4*)(drow + 3);                                \
            float nx = __shfl_down_sync(FULLM, a.x, 1);                       \
            float ny = __shfl_down_sync(FULLM, a.y, 1);                       \
            float nz = __shfl_down_sync(FULLM, a.z, 1);                       \
            float bx0 = __shfl_sync(FULLM, bb.x, 0);                          \
            float by0 = __shfl_sync(FULLM, bb.y, 0);                          \
            float bz0 = __shfl_sync(FULLM, bb.z, 0);                          \
            if (lane == 31) { nx = bx0; ny = by0; nz = bz0; }                 \
            __stcs(d4r + lane, make_float4(a.w, nx, ny, nz));                 \
            float mx2 = __shfl_down_sync(FULLM, bb.x, 1);                     \
            float my2 = __shfl_down_sync(FULLM, bb.y, 1);                     \
            float mz2 = __shfl_down_sync(FULLM, bb.z, 1);                     \
            if (lane < 31) __stcs(d4r + 32 + lane,                            \
                                  make_float4(bb.w, mx2, my2, mz2));          \
            else drow[255] = bb.w;                                            \
            if (p > tv[cK - 1]) {                                             \
                int pos = cK - 1;                                             \
                _Pragma("unroll")                                             \
                for (int j = cK - 1; j > 0; --j)                              \
                    if (tv[j - 1] < p) { tv[j] = tv[j - 1];                   \
                                         ti[j] = ti[j - 1]; pos = j - 1; }    \
                tv[pos] = p; ti[pos] = (RR);                                  \
            }                                                                 \
        }

        int r = wb * WPB + warp;
        for (; r + NWARPS_GEMV < cN; r += 2 * NWARPS_GEMV) {
            ROW_BODY(r);
            ROW_BODY(r + NWARPS_GEMV);
        }
        if (r < cN) ROW_BODY(r);
#undef ROW_BODY

        if (lane == 0) {
#pragma unroll
            for (int j = 0; j < cK; ++j) {
                wv[warp * cK + j] = tv[j];
                wis[warp * cK + j] = ti[j];
            }
        }
        __syncthreads();

        // ---- block merge: warp 0 does 10 rounds of argmax over WPB*10 ----
        if (warp == 0) {
            for (int j = 0; j < cK; ++j) {
                float bv = -3e30f; int bm = 0;
                for (int m = lane; m < WPB * cK; m += 32)
                    if (wv[m] > bv) { bv = wv[m]; bm = m; }
#pragma unroll
                for (int o = 16; o; o >>= 1) {
                    float ov = __shfl_xor_sync(FULLM, bv, o);
                    int   om = __shfl_xor_sync(FULLM, bm, o);
                    if (ov > bv) { bv = ov; bm = om; }
                }
                if (lane == 0) {
                    g_cv[wb * cK + j] = bv;
                    g_ci[wb * cK + j] = wis[bm];
                    wv[bm] = -3e30f;
                }
                __syncwarp();
                __threadfence_block();
            }
        }
        __threadfence();
        __syncthreads();
    }

    // ================= completion ticket =================
    if (t == 0) {
        int v = atomicAdd(&g_ticket, 1);
        is_last = (v == NBLK - 1);
    }
    __syncthreads();
    if (!is_last) return;
    __threadfence();

    // ================= FINAL (last-finishing block) =================
    {
        float* cv   = sm;                   // [0,1460)
        int*   ci   = (int*)(sm + 1472);
        float* mv   = sm + 2944;            // 512
        int*   mi   = (int*)(sm + 3456);    // 512
        float* topv = sm + 3968;
        float* wgt  = sm + 3984;
        int*   topi = (int*)(sm + 4000);
        float* exc2 = sm + 4032;
        float* h2   = sm + 4288;
        float* attn = sm + 4544;
        float* red  = sm + 4800;            // 512

        __syncthreads();
        for (int i = t; i < NCAND; i += TPB) { cv[i] = g_cv[i]; ci[i] = g_ci[i]; }
        if (t < cEXC) exc2[t] = g_exc[t];
        else if (t < 512) h2[t - 256] = hs[(long)(cN - 1) * cHID + (t - 256)];
        __syncthreads();

        for (int j = 0; j < cK; ++j) {
            float bv = -1e30f; int bi = 0;
            for (int i = t; i < NCAND; i += TPB)
                if (cv[i] > bv) { bv = cv[i]; bi = i; }
            mv[t] = bv; mi[t] = bi;
            __syncthreads();
            for (int sft = 256; sft; sft >>= 1) {
                if (t < sft) {
                    if (mv[t + sft] > mv[t]) { mv[t] = mv[t + sft]; mi[t] = mi[t + sft]; }
                }
                __syncthreads();
            }
            if (t == 0) {
                topv[j] = mv[0];
                topi[j] = ci[mi[0]];
                cv[mi[0]] = -3e30f;
            }
            __syncthreads();
        }

        if (t == 0) {
            float mx = topv[0];
            float ssum = 0.f;
            for (int j = 0; j < cK; ++j) { wgt[j] = expf(topv[j] - mx); ssum += wgt[j]; }
            for (int j = 0; j < cK; ++j) wgt[j] /= ssum;
        }
        __syncthreads();

        if (t < cHID) {
            float a = 0.f;
#pragma unroll
            for (int j = 0; j < cK; ++j)
                a += wgt[j] * hs[(long)topi[j] * cHID + t];
            attn[t] = a;
        }
        __syncthreads();

        if (t < 512) {
            float v = (t < cEXC) ? exc2[t] : attn[t - cEXC];
            red[t] = v * out_W[t];
        }
        __syncthreads();
        for (int sft = 256; sft; sft >>= 1) {
            if (t < sft && t + sft < 512) red[t] += red[t + sft];
            __syncthreads();
        }
        if (t == 0) out[OUT_PRED] = red[0] + out_b[0];

        if (t < cHID) {
            float rr = sigmoidf_(g_giv[t] + g_ghv[t]);
            float zz = sigmoidf_(g_giv[cHID + t] + g_ghv[cHID + t]);
            float nn = tanhf(g_giv[2 * cHID + t] + rr * g_ghv[2 * cHID + t]);
            float hn = (1.0f - zz) * nn + zz * h2[t];
            out[OUT_HS + (long)cN * cHID + t] = hn;
        }
        if (t < cEXC)
            out[OUT_EXCS + (long)cN * cEXC + t] = exc2[t];

        if (t == 0) {
            g_gru_done = 0;
            g_ticket = 0;
        }
    }
}

// ============================================================
extern "C" void kernel_launch(void* const* d_in, const int* in_sizes, int n_in,
                              void* d_out, int out_size) {
    const int*   exec_ids = (const int*)d_in[0];
    const float* score    = (const float*)d_in[1];
    const float* excs     = (const float*)d_in[2];
    const float* hs       = (const float*)d_in[3];
    const float* emb      = (const float*)d_in[4];
    const float* wf_Wih   = (const float*)d_in[5];
    const float* wf_Whh   = (const float*)d_in[6];
    const float* wf_bih   = (const float*)d_in[7];
    const float* wf_bhh   = (const float*)d_in[8];
    const float* wb_Wih   = (const float*)d_in[9];
    const float* wb_Whh   = (const float*)d_in[10];
    const float* wb_bih   = (const float*)d_in[11];
    const float* wb_bhh   = (const float*)d_in[12];
    const float* s_Wih    = (const float*)d_in[13];
    const float* s_Whh    = (const float*)d_in[14];
    const float* s_bih    = (const float*)d_in[15];
    const float* s_bhh    = (const float*)d_in[16];
    const float* out_W    = (const float*)d_in[17];
    const float* out_b    = (const float*)d_in[18];
    float* out = (float*)d_out;

    const int fused_smem = FUSED_SMEM_FLOATS * sizeof(float);  // 199,680 B
    cudaFuncSetAttribute(fused_kernel,
                         cudaFuncAttributeMaxDynamicSharedMemorySize, fused_smem);

    gi_kernel<<<128, 384>>>(exec_ids, emb, wf_Wih, wf_bih, wb_Wih, wb_bih);
    fused_kernel<<<NBLK, TPB, fused_smem>>>(score, excs, hs,
                                            wf_Whh, wf_bhh, wb_Whh, wb_bhh,
                                            s_Wih, s_Whh, s_bih, s_bhh,
                                            out_W, out_b, out);
}

// round 5
// speedup vs baseline: 2.0049x; 1.1766x over previous
#include <cuda_runtime.h>
#include <math.h>

// ---------------- problem constants ----------------
#define cL    64
#define cEMB  128
#define cH2   128
#define cG3   384      /* 3*H2 */
#define cEXC  256
#define cHID  256
#define cN    200000
#define cK    10

#define OUT_PRED 0L
#define OUT_EXCS 1L
#define OUT_HS   (1L + (long)(cN + 1) * cEXC)   /* 51200257 */

#define NBLK  148                 /* 2 GRU + 146 workers, exactly 1 wave */
#define NWRK  146
#define TPB   1024
#define WPB   32                  /* warps per block */
#define NWARPS_GEMV (NWRK * WPB)  /* 4672 */
#define NCAND (NWRK * cK)         /* 1460 */
#define FULLM 0xffffffffu

// GRU smem: W 49152 + hbuf 256 + gsh 384 + gin 128 = 49920 floats
#define FUSED_SMEM_FLOATS 49920

// ---------------- device scratch (no allocs allowed) ----------------
__device__ float g_gi[2][cL][cG3];   // precomputed input gates, both dirs
__device__ float g_exc[cEXC];        // max-pooled exercise embedding
__device__ float g_cv[NCAND];        // per-block top-k candidate values
__device__ int   g_ci[NCAND];        // per-block top-k candidate indices
__device__ float g_giv[3 * cHID];    // seq-GRU input-gate preacts
__device__ float g_ghv[3 * cHID];    // seq-GRU hidden-gate preacts
__device__ int   g_gi_done;          // 128 == all gi slices written
__device__ int   g_gru_done;         // 2 == exc ready
__device__ int   g_ticket;           // block completion ticket

__device__ __forceinline__ float sigmoidf_(float x) {
    return 1.0f / (1.0f + expf(-x));
}

// ============================================================
// fused persistent kernel (148 blocks x 1024 threads, 1 wave)
// ============================================================
__global__ void __launch_bounds__(TPB, 1)
fused_kernel(const int* __restrict__ exec_ids,
             const float* __restrict__ emb,
             const float* __restrict__ score,
             const float* __restrict__ excs,
             const float* __restrict__ hs,
             const float* __restrict__ wf_Wih, const float* __restrict__ wf_bih,
             const float* __restrict__ wb_Wih, const float* __restrict__ wb_bih,
             const float* __restrict__ wf_Whh, const float* __restrict__ wf_bhh,
             const float* __restrict__ wb_Whh, const float* __restrict__ wb_bhh,
             const float* __restrict__ s_Wih,  const float* __restrict__ s_Whh,
             const float* __restrict__ s_bih,  const float* __restrict__ s_bhh,
             const float* __restrict__ out_W,  const float* __restrict__ out_b,
             float* __restrict__ out) {
    extern __shared__ float sm[];
    __shared__ int is_last;
    int t = threadIdx.x;
    int lane = t & 31;
    int warp = t >> 5;
    int b = blockIdx.x;

    if (b < 2) {
        // ================= GRU recurrence (dir = b) =================
        int dir = b;
        float* Wsh  = sm;                        // 49152
        float* hbuf = sm + cG3 * cH2;            // 256 (double buffer)
        float* gsh  = hbuf + 256;                // 384
        float* gin  = gsh + 384;                 // 128

        const float* Whh = dir ? wb_Whh : wf_Whh;
        const float* bhh = dir ? wb_bhh : wf_bhh;

        for (int idx = t; idx < cG3 * cH2 / 4; idx += TPB) {
            int kk = idx / cG3;
            int tt = idx - kk * cG3;
            ((float4*)Wsh)[idx] = *(const float4*)(Whh + (long)tt * cH2 + kk * 4);
        }
        if (t < cH2) hbuf[t] = 0.0f;
        float bhh_t = (t < cG3) ? bhh[t] : 0.0f;
        float hmax = -1e30f;

        // wait for gi slices (computed by worker blocks 2..129)
        if (t == 0) {
            while (*(volatile int*)&g_gi_done < 128) __nanosleep(32);
        }
        __syncthreads();
        __threadfence();

        float gi_cur = (t < cG3) ? g_gi[dir][0][t] : 0.0f;

        const float4* W4 = ((const float4*)Wsh) + t;
        for (int s = 0; s < cL; ++s) {
            float gi_nxt = (t < cG3 && s + 1 < cL) ? g_gi[dir][s + 1][t] : 0.0f;
            float* hcur = hbuf + ((s & 1) ? 128 : 0);
            float* hnxt = hbuf + ((s & 1) ? 0 : 128);

            if (t < cG3) {
                const float4* h4 = (const float4*)hcur;
                float a0 = 0.f, a1 = 0.f;
#pragma unroll
                for (int kk = 0; kk < 32; kk += 2) {
                    float4 w = W4[kk * cG3];        float4 hv = h4[kk];
                    a0 += w.x * hv.x + w.y * hv.y + w.z * hv.z + w.w * hv.w;
                    float4 w2 = W4[(kk + 1) * cG3]; float4 hv2 = h4[kk + 1];
                    a1 += w2.x * hv2.x + w2.y * hv2.y + w2.z * hv2.z + w2.w * hv2.w;
                }
                float gh = a0 + a1 + bhh_t;
                if (t < 256) {
                    gsh[t] = sigmoidf_(gi_cur + gh);
                } else {
                    gsh[t] = gh;
                    gin[t - 256] = gi_cur;
                }
            }
            __syncthreads();

            if (t < cH2) {
                float r = gsh[t];
                float z = gsh[128 + t];
                float n = tanhf(gin[t] + r * gsh[256 + t]);
                float hn = (1.0f - z) * n + z * hcur[t];
                hnxt[t] = hn;
                hmax = fmaxf(hmax, hn);
            }
            __syncthreads();
            gi_cur = gi_nxt;
        }
        if (t < cH2) g_exc[dir * cH2 + t] = hmax;
        __threadfence();
        __syncthreads();
        if (t == 0) atomicAdd(&g_gru_done, 1);

        if (t == 0) {
            while (*(volatile int*)&g_gru_done < 2) __nanosleep(64);
        }
        __syncthreads();
        __threadfence();

        // ---- seq-GRU gate preacts: this block handles 384 gates ----
        float* exc_sh = sm;
        float* h_sh   = sm + 256;
        if (t < 256) exc_sh[t] = g_exc[t];
        else if (t < 512) h_sh[t - 256] = hs[(long)(cN - 1) * cHID + (t - 256)];
        __syncthreads();

        int off = (score[0] >= 0.5f) ? 0 : 256;
        const float4* x4  = (const float4*)exc_sh;
        const float4* hh4 = (const float4*)h_sh;
#pragma unroll
        for (int j = 0; j < 12; ++j) {
            int g = dir * 384 + warp * 12 + j;
            const float4* wi4 = (const float4*)(s_Wih + (long)g * 512 + off);
            const float4* wh4 = (const float4*)(s_Whh + (long)g * 256);

            float4 a = wi4[lane];       float4 xa = x4[lane];
            float4 bb = wi4[lane + 32]; float4 xb = x4[lane + 32];
            float giv = a.x * xa.x + a.y * xa.y + a.z * xa.z + a.w * xa.w
                      + bb.x * xb.x + bb.y * xb.y + bb.z * xb.z + bb.w * xb.w;

            float4 c = wh4[lane];       float4 hc = hh4[lane];
            float4 d = wh4[lane + 32];  float4 hd = hh4[lane + 32];
            float ghv = c.x * hc.x + c.y * hc.y + c.z * hc.z + c.w * hc.w
                      + d.x * hd.x + d.y * hd.y + d.z * hd.z + d.w * hd.w;
#pragma unroll
            for (int o = 16; o; o >>= 1) {
                giv += __shfl_xor_sync(FULLM, giv, o);
                ghv += __shfl_xor_sync(FULLM, ghv, o);
            }
            if (lane == 0) {
                g_giv[g] = giv + s_bih[g];
                g_ghv[g] = ghv + s_bhh[g];
            }
        }
        __threadfence();
        __syncthreads();
    } else {
        // ================= worker block =================
        int wb = b - 2;

        // ---- phase 0: blocks 2..129 compute one gi slice each ----
        if (wb < 128) {
            int dir = wb >> 6;
            int s = wb & 63;
            int row = dir ? (cL - 1 - s) : s;
            float* xs = sm + 1024;
            const float* Wih = dir ? wb_Wih : wf_Wih;
            const float* bih = dir ? wb_bih : wf_bih;
            if (t < 32) {
                int wid = exec_ids[row];
                ((float4*)xs)[t] = ((const float4*)(emb + (long)wid * cEMB))[t];
            }
            __syncthreads();
            if (t < cG3) {
                const float4* w4 = (const float4*)(Wih + (long)t * cEMB);
                const float4* xx4 = (const float4*)xs;
                float a0 = 0.f, a1 = 0.f;
#pragma unroll
                for (int k = 0; k < 32; k += 2) {
                    float4 w = w4[k];     float4 x = xx4[k];
                    a0 += w.x * x.x + w.y * x.y + w.z * x.z + w.w * x.w;
                    float4 w2 = w4[k + 1]; float4 x2 = xx4[k + 1];
                    a1 += w2.x * x2.x + w2.y * x2.y + w2.z * x2.z + w2.w * x2.w;
                }
                g_gi[dir][s][t] = a0 + a1 + bih[t];
            }
            __threadfence();
            __syncthreads();
            if (t == 0) atomicAdd(&g_gi_done, 1);
        }

        // head/tail scalars of the misaligned hs region
        if (wb == 0 && t == 1) {
            out[OUT_HS + 0] = hs[0];
            out[OUT_HS + 1] = hs[1];
            out[OUT_HS + 2] = hs[2];
            out[OUT_HS + (long)cN * cHID - 1] = hs[(long)cN * cHID - 1];
        }

        // ---- phase 1: stream copy hs -> out[OUT_HS], aligned STG.128,
        //      shifted-window loads (no shuffles) ----
        {
            const float4* s4 = (const float4*)hs;
            float4* d4 = (float4*)(out + OUT_HS + 3);   // 16B aligned
            const long Q = (long)cN * cHID / 4 - 1;     // 12,799,999
            const long big = (long)NWRK * TPB * 4;
            for (long base = (long)wb * (TPB * 4); base < Q; base += big) {
                long n0 = base + t;
                long n1 = n0 + TPB;
                long n2 = n1 + TPB;
                long n3 = n2 + TPB;
                float4 v0, v1, v2, v3;
                float w0, w1, w2, w3;
                if (n0 < Q) { v0 = __ldcs(s4 + n0 + 1); w0 = __ldcs(hs + 4 * n0 + 3); }
                if (n1 < Q) { v1 = __ldcs(s4 + n1 + 1); w1 = __ldcs(hs + 4 * n1 + 3); }
                if (n2 < Q) { v2 = __ldcs(s4 + n2 + 1); w2 = __ldcs(hs + 4 * n2 + 3); }
                if (n3 < Q) { v3 = __ldcs(s4 + n3 + 1); w3 = __ldcs(hs + 4 * n3 + 3); }
                if (n0 < Q) __stcs(d4 + n0, make_float4(w0, v0.x, v0.y, v0.z));
                if (n1 < Q) __stcs(d4 + n1, make_float4(w1, v1.x, v1.y, v1.z));
                if (n2 < Q) __stcs(d4 + n2, make_float4(w2, v2.x, v2.y, v2.z));
                if (n3 < Q) __stcs(d4 + n3, make_float4(w3, v3.x, v3.y, v3.z));
            }
        }

        // ---- wait for exc ----
        if (t == 0) {
            while (*(volatile int*)&g_gru_done < 2) __nanosleep(128);
        }
        __syncthreads();
        __threadfence();

        float* exc_sh = sm;                           // 256
        float* wv  = sm + 256;                        // WPB*10
        int*   wis = (int*)(sm + 256 + WPB * cK);     // WPB*10
        if (t < cEXC) exc_sh[t] = g_exc[t];
        if (t < WPB * cK) { wv[t] = -1e30f; wis[t] = 0; }
        __syncthreads();

        // ---- phase 2: fused excs copy + alpha gemv + smem top-10 ----
        const int c0 = lane * 4;
        const float e0 = exc_sh[c0],           e1 = exc_sh[c0 + 1];
        const float e2 = exc_sh[c0 + 2],       e3 = exc_sh[c0 + 3];
        const float f0 = exc_sh[128 + c0],     f1 = exc_sh[128 + c0 + 1];
        const float f2 = exc_sh[128 + c0 + 2], f3 = exc_sh[128 + c0 + 3];
        const int wbase = warp * cK;
        float t9 = -1e30f;   // uniform current 10th value of this warp's list

        for (int r = wb * WPB + warp; r < cN; r += NWARPS_GEMV) {
            const float4* rp = (const float4*)(excs + (long)r * cEXC);
            float4 a  = __ldcs(rp + lane);        // quads 0..31
            float4 b2 = __ldcs(rp + 32 + lane);   // quads 32..63
            float4 a1 = __ldcs(rp + lane + 1);    // quads 1..32
            float4 b1 = make_float4(0.f, 0.f, 0.f, 0.f);
            if (lane < 31) b1 = __ldcs(rp + 33 + lane);   // quads 33..63

            float p = a.x * e0 + a.y * e1 + a.z * e2 + a.w * e3
                    + b2.x * f0 + b2.y * f1 + b2.z * f2 + b2.w * f3;
#pragma unroll
            for (int o = 16; o; o >>= 1) p += __shfl_xor_sync(FULLM, p, o);

            float* drow = out + OUT_EXCS + (long)r * cEXC;
            float4* d4r = (float4*)(drow + 3);
            if (lane == 0) { drow[0] = a.x; drow[1] = a.y; drow[2] = a.z; }
            __stcs(d4r + lane, make_float4(a.w, a1.x, a1.y, a1.z));
            if (lane < 31) __stcs(d4r + 32 + lane,
                                  make_float4(b2.w, b1.x, b1.y, b1.z));
            else drow[255] = b2.w;

            if (p > t9) {
                if (lane == 0) {
                    int pos = cK - 1;
                    while (pos > 0 && wv[wbase + pos - 1] < p) {
                        wv[wbase + pos] = wv[wbase + pos - 1];
                        wis[wbase + pos] = wis[wbase + pos - 1];
                        --pos;
                    }
                    wv[wbase + pos] = p;
                    wis[wbase + pos] = r;
                }
                __syncwarp();
                t9 = wv[wbase + cK - 1];
            }
        }
        __syncthreads();

        // ---- block merge: warp 0, 10 rounds of argmax over WPB*10 ----
        if (warp == 0) {
            for (int j = 0; j < cK; ++j) {
                float bv = -3e30f; int bm = 0;
                for (int m = lane; m < WPB * cK; m += 32)
                    if (wv[m] > bv) { bv = wv[m]; bm = m; }
#pragma unroll
                for (int o = 16; o; o >>= 1) {
                    float ov = __shfl_xor_sync(FULLM, bv, o);
                    int   om = __shfl_xor_sync(FULLM, bm, o);
                    if (ov > bv) { bv = ov; bm = om; }
                }
                if (lane == 0) {
                    g_cv[wb * cK + j] = bv;
                    g_ci[wb * cK + j] = wis[bm];
                    wv[bm] = -3e30f;
                }
                __syncwarp();
                __threadfence_block();
            }
        }
        __threadfence();
        __syncthreads();
    }

    // ================= completion ticket =================
    if (t == 0) {
        int v = atomicAdd(&g_ticket, 1);
        is_last = (v == NBLK - 1);
    }
    __syncthreads();
    if (!is_last) return;
    __threadfence();

    // ================= FINAL (last-finishing block) =================
    {
        float* cv   = sm;                   // [0,1460)
        int*   ci   = (int*)(sm + 1472);
        float* mv   = sm + 2944;            // 1024
        int*   mi   = (int*)(sm + 3968);    // 1024
        float* topv = sm + 4992;
        float* wgt  = sm + 5008;
        int*   topi = (int*)(sm + 5024);
        float* exc2 = sm + 5056;
        float* h2   = sm + 5312;
        float* attn = sm + 5568;
        float* red  = sm + 5824;            // 512

        __syncthreads();
        for (int i = t; i < NCAND; i += TPB) { cv[i] = g_cv[i]; ci[i] = g_ci[i]; }
        if (t < cEXC) exc2[t] = g_exc[t];
        else if (t < 512) h2[t - 256] = hs[(long)(cN - 1) * cHID + (t - 256)];
        __syncthreads();

        for (int j = 0; j < cK; ++j) {
            float bv = -1e30f; int bi = 0;
            for (int i = t; i < NCAND; i += TPB)
                if (cv[i] > bv) { bv = cv[i]; bi = i; }
            mv[t] = bv; mi[t] = bi;
            __syncthreads();
            for (int sft = 512; sft; sft >>= 1) {
                if (t < sft) {
                    if (mv[t + sft] > mv[t]) { mv[t] = mv[t + sft]; mi[t] = mi[t + sft]; }
                }
                __syncthreads();
            }
            if (t == 0) {
                topv[j] = mv[0];
                topi[j] = ci[mi[0]];
                cv[mi[0]] = -3e30f;
            }
            __syncthreads();
        }

        if (t == 0) {
            float mx = topv[0];
            float ssum = 0.f;
            for (int j = 0; j < cK; ++j) { wgt[j] = expf(topv[j] - mx); ssum += wgt[j]; }
            for (int j = 0; j < cK; ++j) wgt[j] /= ssum;
        }
        __syncthreads();

        if (t < cHID) {
            float a = 0.f;
#pragma unroll
            for (int j = 0; j < cK; ++j)
                a += wgt[j] * hs[(long)topi[j] * cHID + t];
            attn[t] = a;
        }
        __syncthreads();

        if (t < 512) {
            float v = (t < cEXC) ? exc2[t] : attn[t - cEXC];
            red[t] = v * out_W[t];
        }
        __syncthreads();
        for (int sft = 256; sft; sft >>= 1) {
            if (t < sft) red[t] += red[t + sft];
            __syncthreads();
        }
        if (t == 0) out[OUT_PRED] = red[0] + out_b[0];

        if (t < cHID) {
            float rr = sigmoidf_(g_giv[t] + g_ghv[t]);
            float zz = sigmoidf_(g_giv[cHID + t] + g_ghv[cHID + t]);
            float nn = tanhf(g_giv[2 * cHID + t] + rr * g_ghv[2 * cHID + t]);
            float hn = (1.0f - zz) * nn + zz * h2[t];
            out[OUT_HS + (long)cN * cHID + t] = hn;
        }
        if (t < cEXC)
            out[OUT_EXCS + (long)cN * cEXC + t] = exc2[t];

        if (t == 0) {
            g_gru_done = 0;
            g_ticket = 0;
            g_gi_done = 0;
        }
    }
}

// ============================================================
extern "C" void kernel_launch(void* const* d_in, const int* in_sizes, int n_in,
                              void* d_out, int out_size) {
    const int*   exec_ids = (const int*)d_in[0];
    const float* score    = (const float*)d_in[1];
    const float* excs     = (const float*)d_in[2];
    const float* hs       = (const float*)d_in[3];
    const float* emb      = (const float*)d_in[4];
    const float* wf_Wih   = (const float*)d_in[5];
    const float* wf_Whh   = (const float*)d_in[6];
    const float* wf_bih   = (const float*)d_in[7];
    const float* wf_bhh   = (const float*)d_in[8];
    const float* wb_Wih   = (const float*)d_in[9];
    const float* wb_Whh   = (const float*)d_in[10];
    const float* wb_bih   = (const float*)d_in[11];
    const float* wb_bhh   = (const float*)d_in[12];
    const float* s_Wih    = (const float*)d_in[13];
    const float* s_Whh    = (const float*)d_in[14];
    const float* s_bih    = (const float*)d_in[15];
    const float* s_bhh    = (const float*)d_in[16];
    const float* out_W    = (const float*)d_in[17];
    const float* out_b    = (const float*)d_in[18];
    float* out = (float*)d_out;

    const int fused_smem = FUSED_SMEM_FLOATS * sizeof(float);  // 199,680 B
    cudaFuncSetAttribute(fused_kernel,
                         cudaFuncAttributeMaxDynamicSharedMemorySize, fused_smem);

    fused_kernel<<<NBLK, TPB, fused_smem>>>(exec_ids, emb, score, excs, hs,
                                            wf_Wih, wf_bih, wb_Wih, wb_bih,
                                            wf_Whh, wf_bhh, wb_Whh, wb_bhh,
                                            s_Wih, s_Whh, s_bih, s_bhh,
                                            out_W, out_b, out);
}

// round 6
// speedup vs baseline: 2.0052x; 1.0002x over previous
#include <cuda_runtime.h>
#include <math.h>

// ---------------- problem constants ----------------
#define cL    64
#define cEMB  128
#define cH2   128
#define cG3   384      /* 3*H2 */
#define cEXC  256
#define cHID  256
#define cN    200000
#define cK    10

#define OUT_PRED 0L
#define OUT_EXCS 1L
#define OUT_HS   (1L + (long)(cN + 1) * cEXC)   /* 51200257 */

#define NBLK  148                 /* 2 GRU + 146 workers, exactly 1 wave */
#define NWRK  146
#define TPB   1024
#define WPB   32                  /* warps per block */
#define NWARPS_GEMV (NWRK * WPB)  /* 4672 */
#define NCAND (NWRK * cK)         /* 1460 */
#define FULLM 0xffffffffu

// GRU smem: W 49152 + hbuf 256 + gsh 384 + gin 128 = 49920 floats
#define FUSED_SMEM_FLOATS 49920

// ---------------- device scratch (no allocs allowed) ----------------
__device__ float g_gi[2][cL][cG3];   // precomputed input gates, both dirs
__device__ float g_exc[cEXC];        // max-pooled exercise embedding
__device__ float g_cv[NCAND];        // per-block top-k candidate values
__device__ int   g_ci[NCAND];        // per-block top-k candidate indices
__device__ float g_giv[3 * cHID];    // seq-GRU input-gate preacts
__device__ float g_ghv[3 * cHID];    // seq-GRU hidden-gate preacts
__device__ int   g_gi_done;          // 128 == all gi slices written
__device__ int   g_gru_done;         // 2 == exc ready
__device__ int   g_ticket;           // block completion ticket

__device__ __forceinline__ float sigmoidf_(float x) {
    return 1.0f / (1.0f + expf(-x));
}

// ============================================================
// fused persistent kernel (148 blocks x 1024 threads, 1 wave)
// ============================================================
__global__ void __launch_bounds__(TPB, 1)
fused_kernel(const int* __restrict__ exec_ids,
             const float* __restrict__ emb,
             const float* __restrict__ score,
             const float* __restrict__ excs,
             const float* __restrict__ hs,
             const float* __restrict__ wf_Wih, const float* __restrict__ wf_bih,
             const float* __restrict__ wb_Wih, const float* __restrict__ wb_bih,
             const float* __restrict__ wf_Whh, const float* __restrict__ wf_bhh,
             const float* __restrict__ wb_Whh, const float* __restrict__ wb_bhh,
             const float* __restrict__ s_Wih,  const float* __restrict__ s_Whh,
             const float* __restrict__ s_bih,  const float* __restrict__ s_bhh,
             const float* __restrict__ out_W,  const float* __restrict__ out_b,
             float* __restrict__ out) {
    extern __shared__ float sm[];
    __shared__ int is_last;
    int t = threadIdx.x;
    int lane = t & 31;
    int warp = t >> 5;
    int b = blockIdx.x;

    if (b < 2) {
        // ================= GRU recurrence (dir = b) =================
        int dir = b;
        float* Wsh  = sm;                        // 49152
        float* hbuf = sm + cG3 * cH2;            // 256 (double buffer)
        float* gsh  = hbuf + 256;                // 384
        float* gin  = gsh + 384;                 // 128

        const float* Whh = dir ? wb_Whh : wf_Whh;
        const float* bhh = dir ? wb_bhh : wf_bhh;

        for (int idx = t; idx < cG3 * cH2 / 4; idx += TPB) {
            int kk = idx / cG3;
            int tt = idx - kk * cG3;
            ((float4*)Wsh)[idx] = *(const float4*)(Whh + (long)tt * cH2 + kk * 4);
        }
        if (t < cH2) hbuf[t] = 0.0f;
        float bhh_t = (t < cG3) ? bhh[t] : 0.0f;
        float hmax = -1e30f;

        // wait for gi slices (computed by worker blocks 2..129)
        if (t == 0) {
            while (*(volatile int*)&g_gi_done < 128) __nanosleep(32);
        }
        __syncthreads();
        __threadfence();

        float gi_cur = (t < cG3) ? g_gi[dir][0][t] : 0.0f;

        const float4* W4 = ((const float4*)Wsh) + t;
        for (int s = 0; s < cL; ++s) {
            float gi_nxt = (t < cG3 && s + 1 < cL) ? g_gi[dir][s + 1][t] : 0.0f;
            float* hcur = hbuf + ((s & 1) ? 128 : 0);
            float* hnxt = hbuf + ((s & 1) ? 0 : 128);

            if (t < cG3) {
                const float4* h4 = (const float4*)hcur;
                float a0 = 0.f, a1 = 0.f;
#pragma unroll
                for (int kk = 0; kk < 32; kk += 2) {
                    float4 w = W4[kk * cG3];        float4 hv = h4[kk];
                    a0 += w.x * hv.x + w.y * hv.y + w.z * hv.z + w.w * hv.w;
                    float4 w2 = W4[(kk + 1) * cG3]; float4 hv2 = h4[kk + 1];
                    a1 += w2.x * hv2.x + w2.y * hv2.y + w2.z * hv2.z + w2.w * hv2.w;
                }
                float gh = a0 + a1 + bhh_t;
                if (t < 256) {
                    gsh[t] = sigmoidf_(gi_cur + gh);
                } else {
                    gsh[t] = gh;
                    gin[t - 256] = gi_cur;
                }
            }
            __syncthreads();

            if (t < cH2) {
                float r = gsh[t];
                float z = gsh[128 + t];
                float n = tanhf(gin[t] + r * gsh[256 + t]);
                float hn = (1.0f - z) * n + z * hcur[t];
                hnxt[t] = hn;
                hmax = fmaxf(hmax, hn);
            }
            __syncthreads();
            gi_cur = gi_nxt;
        }
        if (t < cH2) g_exc[dir * cH2 + t] = hmax;
        __threadfence();
        __syncthreads();
        if (t == 0) atomicAdd(&g_gru_done, 1);

        if (t == 0) {
            while (*(volatile int*)&g_gru_done < 2) __nanosleep(64);
        }
        __syncthreads();
        __threadfence();

        // ---- seq-GRU gate preacts: this block handles 384 gates ----
        float* exc_sh = sm;
        float* h_sh   = sm + 256;
        if (t < 256) exc_sh[t] = g_exc[t];
        else if (t < 512) h_sh[t - 256] = hs[(long)(cN - 1) * cHID + (t - 256)];
        __syncthreads();

        int off = (score[0] >= 0.5f) ? 0 : 256;
        const float4* x4  = (const float4*)exc_sh;
        const float4* hh4 = (const float4*)h_sh;
#pragma unroll
        for (int j = 0; j < 12; ++j) {
            int g = dir * 384 + warp * 12 + j;
            const float4* wi4 = (const float4*)(s_Wih + (long)g * 512 + off);
            const float4* wh4 = (const float4*)(s_Whh + (long)g * 256);

            float4 a = wi4[lane];       float4 xa = x4[lane];
            float4 bb = wi4[lane + 32]; float4 xb = x4[lane + 32];
            float giv = a.x * xa.x + a.y * xa.y + a.z * xa.z + a.w * xa.w
                      + bb.x * xb.x + bb.y * xb.y + bb.z * xb.z + bb.w * xb.w;

            float4 c = wh4[lane];       float4 hc = hh4[lane];
            float4 d = wh4[lane + 32];  float4 hd = hh4[lane + 32];
            float ghv = c.x * hc.x + c.y * hc.y + c.z * hc.z + c.w * hc.w
                      + d.x * hd.x + d.y * hd.y + d.z * hd.z + d.w * hd.w;
#pragma unroll
            for (int o = 16; o; o >>= 1) {
                giv += __shfl_xor_sync(FULLM, giv, o);
                ghv += __shfl_xor_sync(FULLM, ghv, o);
            }
            if (lane == 0) {
                g_giv[g] = giv + s_bih[g];
                g_ghv[g] = ghv + s_bhh[g];
            }
        }
        __threadfence();
        __syncthreads();
    } else {
        // ================= worker block =================
        int wb = b - 2;

        // ---- phase 0: blocks 2..129 compute one gi slice each ----
        if (wb < 128) {
            int dir = wb >> 6;
            int s = wb & 63;
            int row = dir ? (cL - 1 - s) : s;
            float* xs = sm + 1024;
            const float* Wih = dir ? wb_Wih : wf_Wih;
            const float* bih = dir ? wb_bih : wf_bih;
            if (t < 32) {
                int wid = exec_ids[row];
                ((float4*)xs)[t] = ((const float4*)(emb + (long)wid * cEMB))[t];
            }
            __syncthreads();
            if (t < cG3) {
                const float4* w4 = (const float4*)(Wih + (long)t * cEMB);
                const float4* xx4 = (const float4*)xs;
                float a0 = 0.f, a1 = 0.f;
#pragma unroll
                for (int k = 0; k < 32; k += 2) {
                    float4 w = w4[k];     float4 x = xx4[k];
                    a0 += w.x * x.x + w.y * x.y + w.z * x.z + w.w * x.w;
                    float4 w2 = w4[k + 1]; float4 x2 = xx4[k + 1];
                    a1 += w2.x * x2.x + w2.y * x2.y + w2.z * x2.z + w2.w * x2.w;
                }
                g_gi[dir][s][t] = a0 + a1 + bih[t];
            }
            __threadfence();
            __syncthreads();
            if (t == 0) atomicAdd(&g_gi_done, 1);
        }

        // head/tail scalars of the misaligned hs region
        if (wb == 0 && t == 1) {
            out[OUT_HS + 0] = hs[0];
            out[OUT_HS + 1] = hs[1];
            out[OUT_HS + 2] = hs[2];
            out[OUT_HS + (long)cN * cHID - 1] = hs[(long)cN * cHID - 1];
        }

        // ---- phase 1: stream copy hs -> out[OUT_HS], aligned STG.128,
        //      shifted-window loads, 6 chunks in flight ----
        {
            const float4* s4 = (const float4*)hs;
            float4* d4 = (float4*)(out + OUT_HS + 3);   // 16B aligned
            const long Q = (long)cN * cHID / 4 - 1;     // 12,799,999
            const long big = (long)NWRK * TPB * 6;
            for (long base = (long)wb * (TPB * 6); base < Q; base += big) {
                long n0 = base + t;
                long n1 = n0 + TPB;
                long n2 = n1 + TPB;
                long n3 = n2 + TPB;
                long n4 = n3 + TPB;
                long n5 = n4 + TPB;
                float4 v0, v1, v2, v3, v4, v5;
                float w0, w1, w2, w3, w4, w5;
                if (n0 < Q) { v0 = __ldcs(s4 + n0 + 1); w0 = __ldcs(hs + 4 * n0 + 3); }
                if (n1 < Q) { v1 = __ldcs(s4 + n1 + 1); w1 = __ldcs(hs + 4 * n1 + 3); }
                if (n2 < Q) { v2 = __ldcs(s4 + n2 + 1); w2 = __ldcs(hs + 4 * n2 + 3); }
                if (n3 < Q) { v3 = __ldcs(s4 + n3 + 1); w3 = __ldcs(hs + 4 * n3 + 3); }
                if (n4 < Q) { v4 = __ldcs(s4 + n4 + 1); w4 = __ldcs(hs + 4 * n4 + 3); }
                if (n5 < Q) { v5 = __ldcs(s4 + n5 + 1); w5 = __ldcs(hs + 4 * n5 + 3); }
                if (n0 < Q) __stcs(d4 + n0, make_float4(w0, v0.x, v0.y, v0.z));
                if (n1 < Q) __stcs(d4 + n1, make_float4(w1, v1.x, v1.y, v1.z));
                if (n2 < Q) __stcs(d4 + n2, make_float4(w2, v2.x, v2.y, v2.z));
                if (n3 < Q) __stcs(d4 + n3, make_float4(w3, v3.x, v3.y, v3.z));
                if (n4 < Q) __stcs(d4 + n4, make_float4(w4, v4.x, v4.y, v4.z));
                if (n5 < Q) __stcs(d4 + n5, make_float4(w5, v5.x, v5.y, v5.z));
            }
        }

        // ---- wait for exc ----
        if (t == 0) {
            while (*(volatile int*)&g_gru_done < 2) __nanosleep(128);
        }
        __syncthreads();
        __threadfence();

        float* exc_sh = sm;                           // 256
        float* wv  = sm + 256;                        // WPB*10
        int*   wis = (int*)(sm + 256 + WPB * cK);     // WPB*10
        if (t < cEXC) exc_sh[t] = g_exc[t];
        if (t < WPB * cK) { wv[t] = -1e30f; wis[t] = 0; }
        __syncthreads();

        // ---- phase 2: fused excs copy + alpha gemv + smem top-10,
        //      2 rows per iteration (MLP x2) ----
        const int c0 = lane * 4;
        const float e0 = exc_sh[c0],           e1 = exc_sh[c0 + 1];
        const float e2 = exc_sh[c0 + 2],       e3 = exc_sh[c0 + 3];
        const float f0 = exc_sh[128 + c0],     f1 = exc_sh[128 + c0 + 1];
        const float f2 = exc_sh[128 + c0 + 2], f3 = exc_sh[128 + c0 + 3];
        const int wbase = warp * cK;
        float t9 = -1e30f;   // uniform current 10th value of this warp's list

#define TOPK_INS(PP, RR)                                                      \
        if ((PP) > t9) {                                                      \
            if (lane == 0) {                                                  \
                int pos = cK - 1;                                             \
                while (pos > 0 && wv[wbase + pos - 1] < (PP)) {               \
                    wv[wbase + pos] = wv[wbase + pos - 1];                    \
                    wis[wbase + pos] = wis[wbase + pos - 1];                  \
                    --pos;                                                    \
                }                                                             \
                wv[wbase + pos] = (PP);                                       \
                wis[wbase + pos] = (RR);                                      \
            }                                                                 \
            __syncwarp();                                                     \
            t9 = wv[wbase + cK - 1];                                          \
        }

#define ROW_STORE(RR, A, B2, A1, B1)                                          \
        {                                                                     \
            float* drow = out + OUT_EXCS + (long)(RR) * cEXC;                 \
            float4* d4r = (float4*)(drow + 3);                                \
            if (lane == 0) { drow[0] = (A).x; drow[1] = (A).y;                \
                             drow[2] = (A).z; }                               \
            __stcs(d4r + lane, make_float4((A).w, (A1).x, (A1).y, (A1).z));   \
            if (lane < 31) __stcs(d4r + 32 + lane,                            \
                          make_float4((B2).w, (B1).x, (B1).y, (B1).z));       \
            else drow[255] = (B2).w;                                          \
        }

        int r = wb * WPB + warp;
        for (; r + NWARPS_GEMV < cN; r += 2 * NWARPS_GEMV) {
            int r2 = r + NWARPS_GEMV;
            const float4* rpA = (const float4*)(excs + (long)r * cEXC);
            const float4* rpB = (const float4*)(excs + (long)r2 * cEXC);
            // issue all 8 loads before any compute
            float4 Aa  = rpA[lane];
            float4 Ab2 = rpA[32 + lane];
            float4 Ba  = rpB[lane];
            float4 Bb2 = rpB[32 + lane];
            float4 Aa1 = rpA[lane + 1];
            float4 Ba1 = rpB[lane + 1];
            float4 Ab1 = make_float4(0.f, 0.f, 0.f, 0.f);
            float4 Bb1 = make_float4(0.f, 0.f, 0.f, 0.f);
            if (lane < 31) { Ab1 = rpA[33 + lane]; Bb1 = rpB[33 + lane]; }

            float pA = Aa.x * e0 + Aa.y * e1 + Aa.z * e2 + Aa.w * e3
                     + Ab2.x * f0 + Ab2.y * f1 + Ab2.z * f2 + Ab2.w * f3;
            float pB = Ba.x * e0 + Ba.y * e1 + Ba.z * e2 + Ba.w * e3
                     + Bb2.x * f0 + Bb2.y * f1 + Bb2.z * f2 + Bb2.w * f3;
#pragma unroll
            for (int o = 16; o; o >>= 1) {
                pA += __shfl_xor_sync(FULLM, pA, o);
                pB += __shfl_xor_sync(FULLM, pB, o);
            }

            ROW_STORE(r,  Aa, Ab2, Aa1, Ab1);
            ROW_STORE(r2, Ba, Bb2, Ba1, Bb1);

            TOPK_INS(pA, r);
            TOPK_INS(pB, r2);
        }
        if (r < cN) {
            const float4* rp = (const float4*)(excs + (long)r * cEXC);
            float4 a  = rp[lane];
            float4 b2 = rp[32 + lane];
            float4 a1 = rp[lane + 1];
            float4 b1 = make_float4(0.f, 0.f, 0.f, 0.f);
            if (lane < 31) b1 = rp[33 + lane];

            float p = a.x * e0 + a.y * e1 + a.z * e2 + a.w * e3
                    + b2.x * f0 + b2.y * f1 + b2.z * f2 + b2.w * f3;
#pragma unroll
            for (int o = 16; o; o >>= 1) p += __shfl_xor_sync(FULLM, p, o);

            ROW_STORE(r, a, b2, a1, b1);
            TOPK_INS(p, r);
        }
#undef ROW_STORE
#undef TOPK_INS
        __syncthreads();

        // ---- block merge: warp 0, 10 rounds of argmax over WPB*10 ----
        if (warp == 0) {
            for (int j = 0; j < cK; ++j) {
                float bv = -3e30f; int bm = 0;
                for (int m = lane; m < WPB * cK; m += 32)
                    if (wv[m] > bv) { bv = wv[m]; bm = m; }
#pragma unroll
                for (int o = 16; o; o >>= 1) {
                    float ov = __shfl_xor_sync(FULLM, bv, o);
                    int   om = __shfl_xor_sync(FULLM, bm, o);
                    if (ov > bv) { bv = ov; bm = om; }
                }
                if (lane == 0) {
                    g_cv[wb * cK + j] = bv;
                    g_ci[wb * cK + j] = wis[bm];
                    wv[bm] = -3e30f;
                }
                __syncwarp();
                __threadfence_block();
            }
        }
        __threadfence();
        __syncthreads();
    }

    // ================= completion ticket =================
    if (t == 0) {
        int v = atomicAdd(&g_ticket, 1);
        is_last = (v == NBLK - 1);
    }
    __syncthreads();
    if (!is_last) return;
    __threadfence();

    // ================= FINAL (last-finishing block) =================
    {
        float* cv   = sm;                   // [0,1460)
        int*   ci   = (int*)(sm + 1472);
        float* mv   = sm + 2944;            // 1024
        int*   mi   = (int*)(sm + 3968);    // 1024
        float* topv = sm + 4992;
        float* wgt  = sm + 5008;
        int*   topi = (int*)(sm + 5024);
        float* exc2 = sm + 5056;
        float* h2   = sm + 5312;
        float* attn = sm + 5568;
        float* red  = sm + 5824;            // 512

        __syncthreads();
        for (int i = t; i < NCAND; i += TPB) { cv[i] = g_cv[i]; ci[i] = g_ci[i]; }
        if (t < cEXC) exc2[t] = g_exc[t];
        else if (t < 512) h2[t - 256] = hs[(long)(cN - 1) * cHID + (t - 256)];
        __syncthreads();

        for (int j = 0; j < cK; ++j) {
            float bv = -1e30f; int bi = 0;
            for (int i = t; i < NCAND; i += TPB)
                if (cv[i] > bv) { bv = cv[i]; bi = i; }
            mv[t] = bv; mi[t] = bi;
            __syncthreads();
            for (int sft = 512; sft; sft >>= 1) {
                if (t < sft) {
                    if (mv[t + sft] > mv[t]) { mv[t] = mv[t + sft]; mi[t] = mi[t + sft]; }
                }
                __syncthreads();
            }
            if (t == 0) {
                topv[j] = mv[0];
                topi[j] = ci[mi[0]];
                cv[mi[0]] = -3e30f;
            }
            __syncthreads();
        }

        if (t == 0) {
            float mx = topv[0];
            float ssum = 0.f;
            for (int j = 0; j < cK; ++j) { wgt[j] = expf(topv[j] - mx); ssum += wgt[j]; }
            for (int j = 0; j < cK; ++j) wgt[j] /= ssum;
        }
        __syncthreads();

        if (t < cHID) {
            float a = 0.f;
#pragma unroll
            for (int j = 0; j < cK; ++j)
                a += wgt[j] * hs[(long)topi[j] * cHID + t];
            attn[t] = a;
        }
        __syncthreads();

        if (t < 512) {
            float v = (t < cEXC) ? exc2[t] : attn[t - cEXC];
            red[t] = v * out_W[t];
        }
        __syncthreads();
        for (int sft = 256; sft; sft >>= 1) {
            if (t < sft) red[t] += red[t + sft];
            __syncthreads();
        }
        if (t == 0) out[OUT_PRED] = red[0] + out_b[0];

        if (t < cHID) {
            float rr = sigmoidf_(g_giv[t] + g_ghv[t]);
            float zz = sigmoidf_(g_giv[cHID + t] + g_ghv[cHID + t]);
            float nn = tanhf(g_giv[2 * cHID + t] + rr * g_ghv[2 * cHID + t]);
            float hn = (1.0f - zz) * nn + zz * h2[t];
            out[OUT_HS + (long)cN * cHID + t] = hn;
        }
        if (t < cEXC)
            out[OUT_EXCS + (long)cN * cEXC + t] = exc2[t];

        if (t == 0) {
            g_gru_done = 0;
            g_ticket = 0;
            g_gi_done = 0;
        }
    }
}

// ============================================================
extern "C" void kernel_launch(void* const* d_in, const int* in_sizes, int n_in,
                              void* d_out, int out_size) {
    const int*   exec_ids = (const int*)d_in[0];
    const float* score    = (const float*)d_in[1];
    const float* excs     = (const float*)d_in[2];
    const float* hs       = (const float*)d_in[3];
    const float* emb      = (const float*)d_in[4];
    const float* wf_Wih   = (const float*)d_in[5];
    const float* wf_Whh   = (const float*)d_in[6];
    const float* wf_bih   = (const float*)d_in[7];
    const float* wf_bhh   = (const float*)d_in[8];
    const float* wb_Wih   = (const float*)d_in[9];
    const float* wb_Whh   = (const float*)d_in[10];
    const float* wb_bih   = (const float*)d_in[11];
    const float* wb_bhh   = (const float*)d_in[12];
    const float* s_Wih    = (const float*)d_in[13];
    const float* s_Whh    = (const float*)d_in[14];
    const float* s_bih    = (const float*)d_in[15];
    const float* s_bhh    = (const float*)d_in[16];
    const float* out_W    = (const float*)d_in[17];
    const float* out_b    = (const float*)d_in[18];
    float* out = (float*)d_out;

    const int fused_smem = FUSED_SMEM_FLOATS * sizeof(float);  // 199,680 B
    cudaFuncSetAttribute(fused_kernel,
                         cudaFuncAttributeMaxDynamicSharedMemorySize, fused_smem);

    fused_kernel<<<NBLK, TPB, fused_smem>>>(exec_ids, emb, score, excs, hs,
                                            wf_Wih, wf_bih, wb_Wih, wb_bih,
                                            wf_Whh, wf_bhh, wb_Whh, wb_bhh,
                                            s_Wih, s_Whh, s_bih, s_bhh,
                                            out_W, out_b, out);
}

// round 7
// speedup vs baseline: 2.0709x; 1.0328x over previous
#include <cuda_runtime.h>
#include <math.h>

// ---------------- problem constants ----------------
#define cL    64
#define cEMB  128
#define cH2   128
#define cG3   384      /* 3*H2 */
#define cEXC  256
#define cHID  256
#define cN    200000
#define cK    10

#define OUT_PRED 0L
#define OUT_EXCS 1L
#define OUT_HS   (1L + (long)(cN + 1) * cEXC)   /* 51200257 */

#define NBLK  148                 /* 2 GRU + 146 workers, exactly 1 wave */
#define TPB   1024
#define NW    4672                /* worker warps: 146 blocks x 32 */
#define NCAND 1460
#define FULLM 0xffffffffu

#define QHS   ((long)cN * cHID / 4 - 1)   /* 12,799,999 shifted f4 slots */
#define G_HS  100000              /* hs granules of 128 f4 (2KB) */
#define G_EX  50000               /* excs granules of 4 rows */
#define NDL   12                  /* max deferred granules per warp (<=11) */

// smem layout (floats): [0,49152) W | [49152,49408) hbuf | [49408,49792) gsh
// | [49792,49920) gin | [49920,50240) wv | [50240,50560) wis | [50560,50688) xs
#define SM_FLOATS 51200
#define WV_OFF 49920
#define WI_OFF 50240
#define XS_OFF 50560

// ---------------- device scratch (no allocs allowed) ----------------
__device__ float g_gi[2][cL][cG3];
__device__ float g_exc[cEXC];
__device__ float g_cv[NCAND];
__device__ int   g_ci[NCAND];
__device__ float g_giv[3 * cHID];
__device__ float g_ghv[3 * cHID];
__device__ int   g_gi_done;
__device__ int   g_gru_done;
__device__ int   g_ticket;

__device__ __forceinline__ float sigmoidf_(float x) {
    return 1.0f / (1.0f + expf(-x));
}

#define BAR384() asm volatile("bar.sync 1, 384;" ::: "memory")

__device__ __forceinline__ void fma_x2(unsigned long long& acc, double w, double h) {
    asm("fma.rn.f32x2 %0, %1, %2, %0;"
        : "+l"(acc)
        : "l"(__double_as_longlong(w)), "l"(__double_as_longlong(h)));
}
__device__ __forceinline__ void unpack_x2(unsigned long long v, float& lo, float& hi) {
    asm("mov.b64 {%0, %1}, %2;" : "=f"(lo), "=f"(hi) : "l"(v));
}

// ============================================================
__global__ void __launch_bounds__(TPB, 1)
fused_kernel(const int* __restrict__ exec_ids,
             const float* __restrict__ emb,
             const float* __restrict__ score,
             const float* __restrict__ excs,
             const float* __restrict__ hs,
             const float* __restrict__ wf_Wih, const float* __restrict__ wf_bih,
             const float* __restrict__ wb_Wih, const float* __restrict__ wb_bih,
             const float* __restrict__ wf_Whh, const float* __restrict__ wf_bhh,
             const float* __restrict__ wb_Whh, const float* __restrict__ wb_bhh,
             const float* __restrict__ s_Wih,  const float* __restrict__ s_Whh,
             const float* __restrict__ s_bih,  const float* __restrict__ s_bhh,
             const float* __restrict__ out_W,  const float* __restrict__ out_b,
             float* __restrict__ out) {
    extern __shared__ float sm[];
    __shared__ int is_last;
    int t = threadIdx.x;
    int lane = t & 31;
    int warp = t >> 5;
    int b = blockIdx.x;

    if (b < 2) {
        // ================= GRU block (dir = b) =================
        if (warp < 12) {   // t < 384: GRU worker threads
            int dir = b;
            float* Wsh  = sm;
            float* hbuf = sm + cG3 * cH2;
            float* gsh  = hbuf + 256;
            float* gin  = gsh + 384;

            const float* Whh = dir ? wb_Whh : wf_Whh;
            const float* bhh = dir ? wb_bhh : wf_bhh;

            for (int idx = t; idx < cG3 * cH2 / 4; idx += 384) {
                int kk = idx / cG3;
                int tt = idx - kk * cG3;
                ((float4*)Wsh)[idx] = *(const float4*)(Whh + (long)tt * cH2 + kk * 4);
            }
            if (t < cH2) hbuf[t] = 0.0f;
            float bhh_t = bhh[t];
            float hmax = -1e30f;

            if (t == 0) {
                while (*(volatile int*)&g_gi_done < 128) __nanosleep(32);
            }
            BAR384();
            __threadfence();

            float gi_cur = g_gi[dir][0][t];
            const double2* W2 = ((const double2*)Wsh) + t;

            for (int s = 0; s < cL; ++s) {
                float gi_nxt = (s + 1 < cL) ? g_gi[dir][s + 1][t] : 0.0f;
                float* hcur = hbuf + ((s & 1) ? 128 : 0);
                float* hnxt = hbuf + ((s & 1) ? 0 : 128);
                const double2* H2 = (const double2*)hcur;

                unsigned long long aA = 0, aB = 0, aC = 0, aD = 0;
#pragma unroll
                for (int kk = 0; kk < 32; kk += 2) {
                    double2 w0 = W2[(long)kk * cG3];
                    double2 h0 = H2[kk];
                    double2 w1 = W2[(long)(kk + 1) * cG3];
                    double2 h1 = H2[kk + 1];
                    fma_x2(aA, w0.x, h0.x);
                    fma_x2(aB, w0.y, h0.y);
                    fma_x2(aC, w1.x, h1.x);
                    fma_x2(aD, w1.y, h1.y);
                }
                float p0, p1, p2, p3, p4, p5, p6, p7;
                unpack_x2(aA, p0, p1);
                unpack_x2(aB, p2, p3);
                unpack_x2(aC, p4, p5);
                unpack_x2(aD, p6, p7);
                float gh = ((p0 + p1) + (p2 + p3)) + ((p4 + p5) + (p6 + p7)) + bhh_t;

                if (t < 256) {
                    gsh[t] = sigmoidf_(gi_cur + gh);
                } else {
                    gsh[t] = gh;
                    gin[t - 256] = gi_cur;
                }
                BAR384();

                if (t < cH2) {
                    float r = gsh[t];
                    float z = gsh[128 + t];
                    float n = tanhf(gin[t] + r * gsh[256 + t]);
                    float hn = (1.0f - z) * n + z * hcur[t];
                    hnxt[t] = hn;
                    hmax = fmaxf(hmax, hn);
                }
                BAR384();
                gi_cur = gi_nxt;
            }
            if (t < cH2) g_exc[dir * cH2 + t] = hmax;
            __threadfence();
            BAR384();
            if (t == 0) atomicAdd(&g_gru_done, 1);

            if (t == 0) {
                while (*(volatile int*)&g_gru_done < 2) __nanosleep(64);
            }
            BAR384();
            __threadfence();

            // ---- seq-GRU gate preacts: 12 warps x 32 gates ----
            const float4* exc4 = (const float4*)g_exc;
            const float4* hr4  = (const float4*)(hs + (long)(cN - 1) * cHID);
            float4 xa = exc4[lane], xb = exc4[32 + lane];
            float4 ha = hr4[lane],  hb = hr4[32 + lane];
            int off = (score[0] >= 0.5f) ? 0 : 256;
#pragma unroll 4
            for (int jj = 0; jj < 32; ++jj) {
                int g = dir * 384 + warp * 32 + jj;
                const float4* wi4 = (const float4*)(s_Wih + (long)g * 512 + off);
                const float4* wh4 = (const float4*)(s_Whh + (long)g * 256);
                float4 a = wi4[lane], bb = wi4[lane + 32];
                float4 c = wh4[lane], d = wh4[lane + 32];
                float giv = a.x * xa.x + a.y * xa.y + a.z * xa.z + a.w * xa.w
                          + bb.x * xb.x + bb.y * xb.y + bb.z * xb.z + bb.w * xb.w;
                float ghv = c.x * ha.x + c.y * ha.y + c.z * ha.z + c.w * ha.w
                          + d.x * hb.x + d.y * hb.y + d.z * hb.z + d.w * hb.w;
#pragma unroll
                for (int o = 16; o; o >>= 1) {
                    giv += __shfl_xor_sync(FULLM, giv, o);
                    ghv += __shfl_xor_sync(FULLM, ghv, o);
                }
                if (lane == 0) {
                    g_giv[g] = giv + s_bih[g];
                    g_ghv[g] = ghv + s_bhh[g];
                }
            }
            __threadfence();
        }
        // warps 12-31 of GRU blocks: idle, meet here
        __syncthreads();
    } else {
        // ================= worker block =================
        int wb = b - 2;
        int gw = wb * 32 + warp;
        float* wv  = sm + WV_OFF;
        int*   wis = (int*)(sm + WI_OFF);

        // ---- gi slices (blocks 2..129) ----
        if (wb < 128) {
            int dir = wb >> 6;
            int s = wb & 63;
            int row = dir ? (cL - 1 - s) : s;
            float* xs = sm + XS_OFF;
            const float* Wih = dir ? wb_Wih : wf_Wih;
            const float* bih = dir ? wb_bih : wf_bih;
            if (t < 32) {
                int wid = exec_ids[row];
                ((float4*)xs)[t] = ((const float4*)(emb + (long)wid * cEMB))[t];
            }
            __syncthreads();
            if (t < cG3) {
                const float4* w4 = (const float4*)(Wih + (long)t * cEMB);
                const float4* xx4 = (const float4*)xs;
                float a0 = 0.f, a1 = 0.f;
#pragma unroll
                for (int k = 0; k < 32; k += 2) {
                    float4 w = w4[k];      float4 x = xx4[k];
                    a0 += w.x * x.x + w.y * x.y + w.z * x.z + w.w * x.w;
                    float4 w2 = w4[k + 1]; float4 x2 = xx4[k + 1];
                    a1 += w2.x * x2.x + w2.y * x2.y + w2.z * x2.z + w2.w * x2.w;
                }
                g_gi[dir][s][t] = a0 + a1 + bih[t];
            }
            __threadfence();
            __syncthreads();
            if (t == 0) atomicAdd(&g_gi_done, 1);
        }

        if (wb == 0 && t == 1) {
            out[OUT_HS + 0] = hs[0];
            out[OUT_HS + 1] = hs[1];
            out[OUT_HS + 2] = hs[2];
            out[OUT_HS + (long)cN * cHID - 1] = hs[(long)cN * cHID - 1];
        }

        // per-warp top-k init
        if (lane < cK) { wv[warp * cK + lane] = -1e30f; wis[warp * cK + lane] = 0; }
        __syncwarp();

        // ---- hs copy: static per-warp granules of 128 f4 ----
        {
            const float4* s4 = (const float4*)hs;
            float4* d4 = (float4*)(out + OUT_HS + 3);
            for (long g = gw; g < G_HS; g += NW) {
                long base = g * 128 + lane;
                long n0 = base, n1 = base + 32, n2 = base + 64, n3 = base + 96;
                float4 v0, v1, v2, v3;
                float w0, w1, w2, w3;
                if (n0 < QHS) { v0 = __ldcs(s4 + n0 + 1); w0 = __ldcs(hs + 4 * n0 + 3); }
                if (n1 < QHS) { v1 = __ldcs(s4 + n1 + 1); w1 = __ldcs(hs + 4 * n1 + 3); }
                if (n2 < QHS) { v2 = __ldcs(s4 + n2 + 1); w2 = __ldcs(hs + 4 * n2 + 3); }
                if (n3 < QHS) { v3 = __ldcs(s4 + n3 + 1); w3 = __ldcs(hs + 4 * n3 + 3); }
                if (n0 < QHS) __stcs(d4 + n0, make_float4(w0, v0.x, v0.y, v0.z));
                if (n1 < QHS) __stcs(d4 + n1, make_float4(w1, v1.x, v1.y, v1.z));
                if (n2 < QHS) __stcs(d4 + n2, make_float4(w2, v2.x, v2.y, v2.z));
                if (n3 < QHS) __stcs(d4 + n3, make_float4(w3, v3.x, v3.y, v3.z));
            }
        }

        // ---- excs: copy always; dot fused when exc ready, else deferred ----
        const int wbase = warp * cK;
        float t9 = -1e30f;
        bool have = false;
        float4 ea, eb;
        int nd = 0;
        int list[NDL];

#define TOPK_INS(PP, RR)                                                      \
        if ((PP) > t9) {                                                      \
            if (lane == 0) {                                                  \
                int pos = cK - 1;                                             \
                while (pos > 0 && wv[wbase + pos - 1] < (PP)) {               \
                    wv[wbase + pos] = wv[wbase + pos - 1];                    \
                    wis[wbase + pos] = wis[wbase + pos - 1];                  \
                    --pos;                                                    \
                }                                                             \
                wv[wbase + pos] = (PP);                                       \
                wis[wbase + pos] = (RR);                                      \
            }                                                                 \
            __syncwarp();                                                     \
            t9 = wv[wbase + cK - 1];                                          \
        }

#define ROW_COPY(RR, DODOT)                                                   \
        {                                                                     \
            const float4* rp = (const float4*)(excs + (long)(RR) * cEXC);     \
            float4 a  = rp[lane];                                             \
            float4 b2 = rp[32 + lane];                                        \
            float4 a1 = rp[lane + 1];                                         \
            float4 b1 = make_float4(0.f, 0.f, 0.f, 0.f);                      \
            if (lane < 31) b1 = rp[33 + lane];                                \
            float* drow = out + OUT_EXCS + (long)(RR) * cEXC;                 \
            float4* d4r = (float4*)(drow + 3);                                \
            if (lane == 0) { drow[0] = a.x; drow[1] = a.y; drow[2] = a.z; }   \
            __stcs(d4r + lane, make_float4(a.w, a1.x, a1.y, a1.z));           \
            if (lane < 31) __stcs(d4r + 32 + lane,                            \
                                  make_float4(b2.w, b1.x, b1.y, b1.z));       \
            else drow[255] = b2.w;                                            \
            if (DODOT) {                                                      \
                float p = a.x * ea.x + a.y * ea.y + a.z * ea.z + a.w * ea.w   \
                        + b2.x * eb.x + b2.y * eb.y + b2.z * eb.z             \
                        + b2.w * eb.w;                                        \
                _Pragma("unroll")                                             \
                for (int o = 16; o; o >>= 1)                                  \
                    p += __shfl_xor_sync(FULLM, p, o);                        \
                TOPK_INS(p, (RR));                                            \
            }                                                                 \
        }

        for (int j = gw; j < G_EX; j += NW) {
            if (!have && *(volatile int*)&g_gru_done == 2) {
                __threadfence();
                ea = ((const float4*)g_exc)[lane];
                eb = ((const float4*)g_exc)[32 + lane];
                have = true;
            }
            int r0 = j * 4;
            if (have) {
                ROW_COPY(r0 + 0, 1);
                ROW_COPY(r0 + 1, 1);
                ROW_COPY(r0 + 2, 1);
                ROW_COPY(r0 + 3, 1);
            } else {
                ROW_COPY(r0 + 0, 0);
                ROW_COPY(r0 + 1, 0);
                ROW_COPY(r0 + 2, 0);
                ROW_COPY(r0 + 3, 0);
                if (nd < NDL) list[nd] = j;
                ++nd;
            }
        }

        // ---- deferred dots (re-read, no stores) ----
        if (nd > 0) {
            if (!have) {
                while (*(volatile int*)&g_gru_done < 2) __nanosleep(64);
                __threadfence();
                ea = ((const float4*)g_exc)[lane];
                eb = ((const float4*)g_exc)[32 + lane];
            }
            int nn = nd < NDL ? nd : NDL;
            for (int i = 0; i < nn; ++i) {
                int r0 = list[i] * 4;
#pragma unroll
                for (int rr = 0; rr < 4; ++rr) {
                    const float4* rp = (const float4*)(excs + (long)(r0 + rr) * cEXC);
                    float4 a  = rp[lane];
                    float4 b2 = rp[32 + lane];
                    float p = a.x * ea.x + a.y * ea.y + a.z * ea.z + a.w * ea.w
                            + b2.x * eb.x + b2.y * eb.y + b2.z * eb.z + b2.w * eb.w;
#pragma unroll
                    for (int o = 16; o; o >>= 1) p += __shfl_xor_sync(FULLM, p, o);
                    TOPK_INS(p, r0 + rr);
                }
            }
        }
#undef ROW_COPY
#undef TOPK_INS
        __syncthreads();

        // ---- block merge: warp 0, 10 rounds over 320 entries ----
        if (warp == 0) {
            for (int j = 0; j < cK; ++j) {
                float bv = -3e30f; int bm = 0;
                for (int m = lane; m < 32 * cK; m += 32)
                    if (wv[m] > bv) { bv = wv[m]; bm = m; }
#pragma unroll
                for (int o = 16; o; o >>= 1) {
                    float ov = __shfl_xor_sync(FULLM, bv, o);
                    int   om = __shfl_xor_sync(FULLM, bm, o);
                    if (ov > bv) { bv = ov; bm = om; }
                }
                if (lane == 0) {
                    g_cv[wb * cK + j] = bv;
                    g_ci[wb * cK + j] = wis[bm];
                    wv[bm] = -3e30f;
                }
                __syncwarp();
                __threadfence_block();
            }
        }
        __threadfence();
        __syncthreads();
    }

    // ================= completion ticket =================
    if (t == 0) {
        int v = atomicAdd(&g_ticket, 1);
        is_last = (v == NBLK - 1);
    }
    __syncthreads();
    if (!is_last) return;
    __threadfence();

    // ================= FINAL (last-finishing block) =================
    {
        float* cv   = sm;                   // [0,1460)
        int*   ci   = (int*)(sm + 1472);
        float* mv   = sm + 2944;            // 1024
        int*   mi   = (int*)(sm + 3968);    // 1024
        float* topv = sm + 4992;
        float* wgt  = sm + 5008;
        int*   topi = (int*)(sm + 5024);
        float* exc2 = sm + 5056;
        float* h2   = sm + 5312;
        float* attn = sm + 5568;
        float* red  = sm + 5824;            // 512

        __syncthreads();
        for (int i = t; i < NCAND; i += TPB) { cv[i] = g_cv[i]; ci[i] = g_ci[i]; }
        if (t < cEXC) exc2[t] = g_exc[t];
        else if (t < 512) h2[t - 256] = hs[(long)(cN - 1) * cHID + (t - 256)];
        __syncthreads();

        for (int j = 0; j < cK; ++j) {
            float bv = -1e30f; int bi = 0;
            for (int i = t; i < NCAND; i += TPB)
                if (cv[i] > bv) { bv = cv[i]; bi = i; }
            mv[t] = bv; mi[t] = bi;
            __syncthreads();
            for (int sft = 512; sft; sft >>= 1) {
                if (t < sft) {
                    if (mv[t + sft] > mv[t]) { mv[t] = mv[t + sft]; mi[t] = mi[t + sft]; }
                }
                __syncthreads();
            }
            if (t == 0) {
                topv[j] = mv[0];
                topi[j] = ci[mi[0]];
                cv[mi[0]] = -3e30f;
            }
            __syncthreads();
        }

        if (t == 0) {
            float mx = topv[0];
            float ssum = 0.f;
            for (int j = 0; j < cK; ++j) { wgt[j] = expf(topv[j] - mx); ssum += wgt[j]; }
            for (int j = 0; j < cK; ++j) wgt[j] /= ssum;
        }
        __syncthreads();

        if (t < cHID) {
            float a = 0.f;
#pragma unroll
            for (int j = 0; j < cK; ++j)
                a += wgt[j] * hs[(long)topi[j] * cHID + t];
            attn[t] = a;
        }
        __syncthreads();

        if (t < 512) {
            float v = (t < cEXC) ? exc2[t] : attn[t - cEXC];
            red[t] = v * out_W[t];
        }
        __syncthreads();
        for (int sft = 256; sft; sft >>= 1) {
            if (t < sft) red[t] += red[t + sft];
            __syncthreads();
        }
        if (t == 0) out[OUT_PRED] = red[0] + out_b[0];

        if (t < cHID) {
            float rr = sigmoidf_(g_giv[t] + g_ghv[t]);
            float zz = sigmoidf_(g_giv[cHID + t] + g_ghv[cHID + t]);
            float nn = tanhf(g_giv[2 * cHID + t] + rr * g_ghv[2 * cHID + t]);
            float hn = (1.0f - zz) * nn + zz * h2[t];
            out[OUT_HS + (long)cN * cHID + t] = hn;
        }
        if (t < cEXC)
            out[OUT_EXCS + (long)cN * cEXC + t] = exc2[t];

        if (t == 0) {
            g_gru_done = 0;
            g_ticket = 0;
            g_gi_done = 0;
        }
    }
}

// ============================================================
extern "C" void kernel_launch(void* const* d_in, const int* in_sizes, int n_in,
                              void* d_out, int out_size) {
    const int*   exec_ids = (const int*)d_in[0];
    const float* score    = (const float*)d_in[1];
    const float* excs     = (const float*)d_in[2];
    const float* hs       = (const float*)d_in[3];
    const float* emb      = (const float*)d_in[4];
    const float* wf_Wih   = (const float*)d_in[5];
    const float* wf_Whh   = (const float*)d_in[6];
    const float* wf_bih   = (const float*)d_in[7];
    const float* wf_bhh   = (const float*)d_in[8];
    const float* wb_Wih   = (const float*)d_in[9];
    const float* wb_Whh   = (const float*)d_in[10];
    const float* wb_bih   = (const float*)d_in[11];
    const float* wb_bhh   = (const float*)d_in[12];
    const float* s_Wih    = (const float*)d_in[13];
    const float* s_Whh    = (const float*)d_in[14];
    const float* s_bih    = (const float*)d_in[15];
    const float* s_bhh    = (const float*)d_in[16];
    const float* out_W    = (const float*)d_in[17];
    const float* out_b    = (const float*)d_in[18];
    float* out = (float*)d_out;

    const int fused_smem = SM_FLOATS * sizeof(float);  // 204,800 B
    cudaFuncSetAttribute(fused_kernel,
                         cudaFuncAttributeMaxDynamicSharedMemorySize, fused_smem);

    fused_kernel<<<NBLK, TPB, fused_smem>>>(exec_ids, emb, score, excs, hs,
                                            wf_Wih, wf_bih, wb_Wih, wb_bih,
                                            wf_Whh, wf_bhh, wb_Whh, wb_bhh,
                                            s_Wih, s_Whh, s_bih, s_bhh,
                                            out_W, out_b, out);
}